// round 6
// baseline (speedup 1.0000x reference)
#include <cuda_runtime.h>
#include <math.h>

// ---------------- problem constants ----------------
#define B_    32
#define L_    256
#define PD_   164
#define D_    240
#define H_    16
#define NB_   6
#define NC_   250
#define DK_   15
#define HID_  480
#define LP_   257          // L + 1 (CLS)
#define T_EMB (B_*L_)      // 8192 tokens pre-CLS
#define T_ALL (B_*LP_)     // 8224 tokens incl CLS
#define SCALE_ 0.25819888974716115f   // 1/sqrt(15)

// ---------------- scratch (device globals; no allocation allowed) ----------------
__device__ float g_h [T_ALL * D_];
__device__ float g_y [T_ALL * D_];
__device__ float g_q [T_ALL * D_];
__device__ float g_k [T_ALL * D_];
__device__ float g_v [T_ALL * D_];
__device__ float g_o [T_ALL * D_];
__device__ float g_f [T_ALL * HID_];   // also reused as embed intermediate (8192x480 fits)
__device__ float g_mask[T_ALL];

// ---------------- generic tiled GEMM: C = [R +] A@W + bias, opt ReLU ----------------
// A: [M,K] row-major, W: [K,N] row-major. Requires K%4==0, N%4==0.
#define BM 64
#define BN 64
#define BKT 16

template<int RELU, int RES>
__global__ __launch_bounds__(256)
void gemm_k(const float* __restrict__ A, const float* __restrict__ W,
            const float* __restrict__ bias, const float* __restrict__ R,
            float* __restrict__ C, int M, int N, int K)
{
    __shared__ __align__(16) float sA[BKT][BM + 4];
    __shared__ __align__(16) float sW[BKT][BN + 4];

    const int tid = threadIdx.x;
    const int m0 = blockIdx.y * BM;
    const int n0 = blockIdx.x * BN;
    const int tx = tid & 15;          // col group
    const int ty = tid >> 4;          // row group
    const int arow = tid >> 2;        // 0..63
    const int aseg = (tid & 3) * 4;   // 0,4,8,12
    const int wrow = tid >> 4;        // 0..15
    const int wseg = (tid & 15) * 4;  // 0..60

    float acc[4][4];
    #pragma unroll
    for (int i = 0; i < 4; i++)
        #pragma unroll
        for (int j = 0; j < 4; j++) acc[i][j] = 0.f;

    for (int k0 = 0; k0 < K; k0 += BKT) {
        // --- load A tile (transposed into sA[k][m]) ---
        float4 av = make_float4(0.f, 0.f, 0.f, 0.f);
        {
            int gm = m0 + arow, gk = k0 + aseg;
            if (gm < M && gk < K)
                av = *(const float4*)(A + (size_t)gm * K + gk);
        }
        sA[aseg + 0][arow] = av.x;
        sA[aseg + 1][arow] = av.y;
        sA[aseg + 2][arow] = av.z;
        sA[aseg + 3][arow] = av.w;
        // --- load W tile ---
        float4 wv = make_float4(0.f, 0.f, 0.f, 0.f);
        {
            int gk = k0 + wrow, gn = n0 + wseg;
            if (gk < K && gn < N)
                wv = *(const float4*)(W + (size_t)gk * N + gn);
        }
        *(float4*)&sW[wrow][wseg] = wv;
        __syncthreads();

        #pragma unroll
        for (int kk = 0; kk < BKT; kk++) {
            float4 a4 = *(const float4*)&sA[kk][ty * 4];
            float4 w4 = *(const float4*)&sW[kk][tx * 4];
            float ar[4] = {a4.x, a4.y, a4.z, a4.w};
            float wr[4] = {w4.x, w4.y, w4.z, w4.w};
            #pragma unroll
            for (int i = 0; i < 4; i++)
                #pragma unroll
                for (int j = 0; j < 4; j++)
                    acc[i][j] = fmaf(ar[i], wr[j], acc[i][j]);
        }
        __syncthreads();
    }

    const int gn = n0 + tx * 4;
    if (gn >= N) return;
    float4 bv = *(const float4*)(bias + gn);
    #pragma unroll
    for (int i = 0; i < 4; i++) {
        int gm = m0 + ty * 4 + i;
        if (gm >= M) continue;
        float4 out;
        out.x = acc[i][0] + bv.x;
        out.y = acc[i][1] + bv.y;
        out.z = acc[i][2] + bv.z;
        out.w = acc[i][3] + bv.w;
        if (RES) {
            float4 r = *(const float4*)(R + (size_t)gm * N + gn);
            out.x += r.x; out.y += r.y; out.z += r.z; out.w += r.w;
        }
        if (RELU) {
            out.x = fmaxf(out.x, 0.f); out.y = fmaxf(out.y, 0.f);
            out.z = fmaxf(out.z, 0.f); out.w = fmaxf(out.w, 0.f);
        }
        *(float4*)(C + (size_t)gm * N + gn) = out;
    }
}

// ---------------- LayerNorm (warp per token), optional ReLU ----------------
template<int RELU>
__global__ void ln_k(const float* __restrict__ X, const float* __restrict__ g,
                     const float* __restrict__ b, float* __restrict__ Y,
                     int T, int N)
{
    int wid = threadIdx.x >> 5, lane = threadIdx.x & 31;
    int t = blockIdx.x * (blockDim.x >> 5) + wid;
    if (t >= T) return;
    const float* x = X + (size_t)t * N;
    float s = 0.f;
    for (int i = lane; i < N; i += 32) s += x[i];
    #pragma unroll
    for (int o = 16; o; o >>= 1) s += __shfl_xor_sync(~0u, s, o);
    float mean = s / (float)N;
    float v = 0.f;
    for (int i = lane; i < N; i += 32) { float d = x[i] - mean; v = fmaf(d, d, v); }
    #pragma unroll
    for (int o = 16; o; o >>= 1) v += __shfl_xor_sync(~0u, v, o);
    float inv = rsqrtf(v / (float)N + 1e-5f);
    float* y = Y + (size_t)t * N;
    for (int i = lane; i < N; i += 32) {
        float r = (x[i] - mean) * inv * g[i] + b[i];
        if (RELU) r = fmaxf(r, 0.f);
        y[i] = r;
    }
}

// ---------------- padding mask (warp per token) ----------------
__global__ void mask_k(const float* __restrict__ x, float* __restrict__ mask)
{
    int wid = threadIdx.x >> 5, lane = threadIdx.x & 31;
    int token = blockIdx.x * (blockDim.x >> 5) + wid;
    if (token >= T_EMB) return;
    int b = token / L_, l = token % L_;
    const float* row = x + (size_t)token * PD_;
    float m = -3.4e38f;
    for (int i = lane; i < PD_; i += 32) m = fmaxf(m, row[i]);
    #pragma unroll
    for (int o = 16; o; o >>= 1) m = fmaxf(m, __shfl_xor_sync(~0u, m, o));
    if (lane == 0) {
        mask[b * LP_ + 1 + l] = (m == 0.f) ? 1.f : 0.f;
        if (l == 0) mask[b * LP_] = 0.f;   // CLS always valid
    }
}

// ---------------- assemble: h = concat(cls, embed + pos) ----------------
__global__ void assemble_k(const float* __restrict__ t2, const float* __restrict__ pos,
                           const float* __restrict__ cls, float* __restrict__ h)
{
    int idx = blockIdx.x * blockDim.x + threadIdx.x;
    if (idx >= T_ALL * D_) return;
    int d = idx % D_;
    int bt = idx / D_;
    int t = bt % LP_;
    int b = bt / LP_;
    float v;
    if (t == 0) v = cls[d];
    else        v = t2[((size_t)b * L_ + (t - 1)) * D_ + d] + pos[(size_t)(t - 1) * D_ + d];
    h[idx] = v;
}

// ---------------- attention: block per (head, batch), warp per query ----------------
__global__ __launch_bounds__(256)
void attn_k(const float* __restrict__ q, const float* __restrict__ k,
            const float* __restrict__ v, const float* __restrict__ mask,
            float* __restrict__ o)
{
    const int hh = blockIdx.x;
    const int b  = blockIdx.y;
    __shared__ float sK[LP_][DK_];
    __shared__ float sV[LP_][DK_];
    __shared__ float sQ[LP_][DK_];
    __shared__ float sM[LP_];

    const int tid = threadIdx.x;
    const size_t base = ((size_t)b * LP_) * D_ + hh * DK_;
    for (int idx = tid; idx < LP_ * DK_; idx += blockDim.x) {
        int t = idx / DK_, d = idx % DK_;
        size_t g = base + (size_t)t * D_ + d;
        sK[t][d] = k[g];
        sV[t][d] = v[g];
        sQ[t][d] = q[g];
    }
    for (int t = tid; t < LP_; t += blockDim.x) sM[t] = mask[b * LP_ + t];
    __syncthreads();

    const int wid = tid >> 5, lane = tid & 31;
    for (int qi = wid; qi < LP_; qi += 8) {
        float qv[DK_];
        #pragma unroll
        for (int d = 0; d < DK_; d++) qv[d] = sQ[qi][d];

        float s[9];
        float lmax = -3.4e38f;
        #pragma unroll
        for (int it = 0; it < 9; it++) {
            int j = lane + it * 32;
            float sc = -3.4e38f;
            if (j < LP_) {
                float acc = 0.f;
                #pragma unroll
                for (int d = 0; d < DK_; d++) acc = fmaf(qv[d], sK[j][d], acc);
                sc = (sM[j] != 0.f) ? -10000.f : acc * SCALE_;
            }
            s[it] = sc;
            lmax = fmaxf(lmax, sc);
        }
        #pragma unroll
        for (int off = 16; off; off >>= 1) lmax = fmaxf(lmax, __shfl_xor_sync(~0u, lmax, off));

        float lsum = 0.f;
        #pragma unroll
        for (int it = 0; it < 9; it++) {
            int j = lane + it * 32;
            float p = 0.f;
            if (j < LP_) p = __expf(s[it] - lmax);
            s[it] = p;
            lsum += p;
        }
        #pragma unroll
        for (int off = 16; off; off >>= 1) lsum += __shfl_xor_sync(~0u, lsum, off);
        float inv = 1.f / lsum;

        float oacc[DK_];
        #pragma unroll
        for (int d = 0; d < DK_; d++) oacc[d] = 0.f;
        #pragma unroll
        for (int it = 0; it < 9; it++) {
            int j = lane + it * 32;
            if (j < LP_) {
                float p = s[it];
                #pragma unroll
                for (int d = 0; d < DK_; d++) oacc[d] = fmaf(p, sV[j][d], oacc[d]);
            }
        }
        #pragma unroll
        for (int d = 0; d < DK_; d++) {
            #pragma unroll
            for (int off = 16; off; off >>= 1)
                oacc[d] += __shfl_xor_sync(~0u, oacc[d], off);
        }
        if (lane == 0) {
            size_t og = base + (size_t)qi * D_;
            #pragma unroll
            for (int d = 0; d < DK_; d++) o[og + d] = oacc[d] * inv;
        }
    }
}

// ---------------- masked mean pool + logits (block per batch) ----------------
__global__ __launch_bounds__(256)
void pool_k(const float* __restrict__ h, const float* __restrict__ mask,
            const float* __restrict__ lw, const float* __restrict__ lb,
            float* __restrict__ out)
{
    int b = blockIdx.x;
    __shared__ float sp[D_];
    __shared__ float sm[LP_];
    int tid = threadIdx.x;
    for (int t = tid; t < LP_; t += blockDim.x) sm[t] = mask[b * LP_ + t];
    __syncthreads();
    float cnt = 0.f;
    for (int t = 0; t < LP_; t++) cnt += 1.f - sm[t];
    if (tid < D_) {
        float acc = 0.f;
        for (int t = 0; t < LP_; t++) {
            float w = 1.f - sm[t];
            acc = fmaf(h[((size_t)b * LP_ + t) * D_ + tid], w, acc);
        }
        sp[tid] = acc / cnt;
    }
    __syncthreads();
    if (tid < NC_) {
        float acc = lb[tid];
        for (int d = 0; d < D_; d++) acc = fmaf(sp[d], lw[(size_t)d * NC_ + tid], acc);
        out[b * NC_ + tid] = acc;
    }
}

// ---------------- host launch ----------------
static inline void launch_gemm(const float* A, const float* W, const float* bias,
                               const float* R, float* C, int M, int N, int K,
                               int relu, int res)
{
    dim3 grid((N + BN - 1) / BN, (M + BM - 1) / BM);
    if (res)       gemm_k<0,1><<<grid, 256>>>(A, W, bias, R, C, M, N, K);
    else if (relu) gemm_k<1,0><<<grid, 256>>>(A, W, bias, R, C, M, N, K);
    else           gemm_k<0,0><<<grid, 256>>>(A, W, bias, R, C, M, N, K);
}

extern "C" void kernel_launch(void* const* d_in, const int* in_sizes, int n_in,
                              void* d_out, int out_size)
{
    const float* x       = (const float*)d_in[0];
    const float* pos     = (const float*)d_in[1];
    const float* cls     = (const float*)d_in[2];
    const float* e_W1    = (const float*)d_in[3];
    const float* e_b1    = (const float*)d_in[4];
    const float* e_g1    = (const float*)d_in[5];
    const float* e_bn1   = (const float*)d_in[6];
    const float* e_W2    = (const float*)d_in[7];
    const float* e_b2    = (const float*)d_in[8];
    const float* e_g2    = (const float*)d_in[9];
    const float* e_bn2   = (const float*)d_in[10];
    const float* ln1_g   = (const float*)d_in[11];
    const float* ln1_b   = (const float*)d_in[12];
    const float* Wq      = (const float*)d_in[13];
    const float* bq      = (const float*)d_in[14];
    const float* Wk      = (const float*)d_in[15];
    const float* bk      = (const float*)d_in[16];
    const float* Wv      = (const float*)d_in[17];
    const float* bv      = (const float*)d_in[18];
    const float* Wo      = (const float*)d_in[19];
    const float* bo      = (const float*)d_in[20];
    const float* ln2_g   = (const float*)d_in[21];
    const float* ln2_b   = (const float*)d_in[22];
    const float* W1      = (const float*)d_in[23];
    const float* b1      = (const float*)d_in[24];
    const float* W2      = (const float*)d_in[25];
    const float* b2      = (const float*)d_in[26];
    const float* logit_W = (const float*)d_in[27];
    const float* logit_b = (const float*)d_in[28];
    float* out = (float*)d_out;

    float *h, *y, *q, *k, *v, *o, *f, *msk;
    cudaGetSymbolAddress((void**)&h,   g_h);
    cudaGetSymbolAddress((void**)&y,   g_y);
    cudaGetSymbolAddress((void**)&q,   g_q);
    cudaGetSymbolAddress((void**)&k,   g_k);
    cudaGetSymbolAddress((void**)&v,   g_v);
    cudaGetSymbolAddress((void**)&o,   g_o);
    cudaGetSymbolAddress((void**)&f,   g_f);
    cudaGetSymbolAddress((void**)&msk, g_mask);

    // ---- padding mask ----
    mask_k<<<(T_EMB + 7) / 8, 256>>>(x, msk);

    // ---- XEmbed ----
    launch_gemm(x, e_W1, e_b1, nullptr, f, T_EMB, HID_, PD_, 0, 0);
    ln_k<1><<<(T_EMB + 7) / 8, 256>>>(f, e_g1, e_bn1, f, T_EMB, HID_);
    launch_gemm(f, e_W2, e_b2, nullptr, y, T_EMB, D_, HID_, 0, 0);
    ln_k<1><<<(T_EMB + 7) / 8, 256>>>(y, e_g2, e_bn2, y, T_EMB, D_);
    assemble_k<<<(T_ALL * D_ + 255) / 256, 256>>>(y, pos, cls, h);

    // ---- transformer blocks ----
    for (int i = 0; i < NB_; i++) {
        ln_k<0><<<(T_ALL + 7) / 8, 256>>>(h, ln1_g + i * D_, ln1_b + i * D_, y, T_ALL, D_);
        launch_gemm(y, Wq + (size_t)i * D_ * D_, bq + i * D_, nullptr, q, T_ALL, D_, D_, 0, 0);
        launch_gemm(y, Wk + (size_t)i * D_ * D_, bk + i * D_, nullptr, k, T_ALL, D_, D_, 0, 0);
        launch_gemm(y, Wv + (size_t)i * D_ * D_, bv + i * D_, nullptr, v, T_ALL, D_, D_, 0, 0);
        attn_k<<<dim3(H_, B_), 256>>>(q, k, v, msk, o);
        launch_gemm(o, Wo + (size_t)i * D_ * D_, bo + i * D_, h, h, T_ALL, D_, D_, 0, 1);
        ln_k<0><<<(T_ALL + 7) / 8, 256>>>(h, ln2_g + i * D_, ln2_b + i * D_, y, T_ALL, D_);
        launch_gemm(y, W1 + (size_t)i * D_ * HID_, b1 + i * HID_, nullptr, f, T_ALL, HID_, D_, 1, 0);
        launch_gemm(f, W2 + (size_t)i * HID_ * D_, b2 + i * D_, h, h, T_ALL, D_, HID_, 0, 1);
    }

    // ---- pool + logits ----
    pool_k<<<B_, 256>>>(h, msk, logit_W, logit_b, out);
}

// round 11
// speedup vs baseline: 1.3373x; 1.3373x over previous
#include <cuda_runtime.h>
#include <math.h>

// ---------------- problem constants ----------------
#define B_    32
#define L_    256
#define PD_   164
#define D_    240
#define H_    16
#define NB_   6
#define NC_   250
#define DK_   15
#define DKP_  16           // padded head dim for float4
#define HID_  480
#define LP_   257          // L + 1 (CLS)
#define T_EMB (B_*L_)      // 8192 tokens pre-CLS
#define T_ALL (B_*LP_)     // 8224 tokens incl CLS
#define SCALE_ 0.25819888974716115f   // 1/sqrt(15)
#define QKVN_ 720          // 3*D

// ---------------- scratch (device globals; no allocation allowed) ----------------
__device__ float g_h   [T_ALL * D_];
__device__ float g_y   [T_ALL * D_];
__device__ float g_qkv [T_ALL * QKVN_];
__device__ float g_o   [T_ALL * D_];
__device__ float g_f   [T_ALL * HID_];   // FFN hidden; also embed intermediate
__device__ float g_mask[T_ALL];
__device__ float g_wqkv[NB_ * D_ * QKVN_];
__device__ float g_bqkv[NB_ * QKVN_];

// ---------------- pack QKV weights: [D, 3D] per layer ----------------
__global__ void packqkv_k(const float* __restrict__ Wq, const float* __restrict__ Wk,
                          const float* __restrict__ Wv, const float* __restrict__ bq,
                          const float* __restrict__ bk, const float* __restrict__ bv,
                          float* __restrict__ W, float* __restrict__ bias)
{
    int idx = blockIdx.x * blockDim.x + threadIdx.x;
    const int total = NB_ * D_ * QKVN_;
    if (idx < total) {
        int c = idx % QKVN_;
        int r = (idx / QKVN_) % D_;
        int i = idx / (QKVN_ * D_);
        const float* src = (c < D_) ? Wq : ((c < 2 * D_) ? Wk : Wv);
        int cc = c % D_;
        W[idx] = src[((size_t)i * D_ + r) * D_ + cc];
    }
    if (idx < NB_ * QKVN_) {
        int c = idx % QKVN_;
        int i = idx / QKVN_;
        const float* sb = (c < D_) ? bq : ((c < 2 * D_) ? bk : bv);
        bias[idx] = sb[i * D_ + c % D_];
    }
}

// ---------------- SGEMM 128x128x8, 8x8 microtile, double-buffered ----------------
// C = [R +] A@W + bias, optional ReLU.  A:[M,K] W:[K,N] row-major. K%4==0, N%4==0.
#define GBM 128
#define GBN 128
#define GBK 8

__device__ __forceinline__ float4 ld_a4(const float* __restrict__ A, int M, int K,
                                        int gm, int gk)
{
    if (gm < M && gk < K) return *(const float4*)(A + (size_t)gm * K + gk);
    return make_float4(0.f, 0.f, 0.f, 0.f);
}
__device__ __forceinline__ float4 ld_w4(const float* __restrict__ W, int K, int N,
                                        int gk, int gn)
{
    if (gk < K && gn < N) return *(const float4*)(W + (size_t)gk * N + gn);
    return make_float4(0.f, 0.f, 0.f, 0.f);
}

template<int RELU, int RES>
__global__ __launch_bounds__(256)
void gemm_k(const float* __restrict__ A, const float* __restrict__ W,
            const float* __restrict__ bias, const float* __restrict__ R,
            float* __restrict__ C, int M, int N, int K)
{
    __shared__ __align__(16) float sA[2][GBK][GBM];
    __shared__ __align__(16) float sW[2][GBK][GBN];

    const int tid = threadIdx.x;
    const int m0 = blockIdx.y * GBM;
    const int n0 = blockIdx.x * GBN;

    // load mapping
    const int arow = tid >> 1;          // 0..127
    const int aseg = (tid & 1) * 4;     // 0 or 4
    const int wrow = tid >> 5;          // 0..7
    const int wcol = (tid & 31) * 4;    // 0..124

    // compute mapping
    const int tx = tid & 15;
    const int ty = tid >> 4;
    const int ty4 = ty * 4;
    const int tx4 = tx * 4;

    float acc[8][8];
    #pragma unroll
    for (int i = 0; i < 8; i++)
        #pragma unroll
        for (int j = 0; j < 8; j++) acc[i][j] = 0.f;

    const int kIters = (K + GBK - 1) / GBK;

    // prologue: tile 0
    {
        float4 av = ld_a4(A, M, K, m0 + arow, 0 + aseg);
        float4 wv = ld_w4(W, K, N, 0 + wrow, n0 + wcol);
        sA[0][aseg + 0][arow] = av.x;
        sA[0][aseg + 1][arow] = av.y;
        sA[0][aseg + 2][arow] = av.z;
        sA[0][aseg + 3][arow] = av.w;
        *(float4*)&sW[0][wrow][wcol] = wv;
    }
    __syncthreads();

    for (int it = 0; it < kIters; it++) {
        const int nxt = it + 1;
        float4 aN, wN;
        if (nxt < kIters) {
            aN = ld_a4(A, M, K, m0 + arow, nxt * GBK + aseg);
            wN = ld_w4(W, K, N, nxt * GBK + wrow, n0 + wcol);
        }
        const int buf = it & 1;
        #pragma unroll
        for (int kk = 0; kk < GBK; kk++) {
            float4 a0 = *(const float4*)&sA[buf][kk][ty4];
            float4 a1 = *(const float4*)&sA[buf][kk][ty4 + 64];
            float4 b0 = *(const float4*)&sW[buf][kk][tx4];
            float4 b1 = *(const float4*)&sW[buf][kk][tx4 + 64];
            float av[8] = {a0.x, a0.y, a0.z, a0.w, a1.x, a1.y, a1.z, a1.w};
            float bw[8] = {b0.x, b0.y, b0.z, b0.w, b1.x, b1.y, b1.z, b1.w};
            #pragma unroll
            for (int i = 0; i < 8; i++)
                #pragma unroll
                for (int j = 0; j < 8; j++)
                    acc[i][j] = fmaf(av[i], bw[j], acc[i][j]);
        }
        if (nxt < kIters) {
            const int nbuf = nxt & 1;
            sA[nbuf][aseg + 0][arow] = aN.x;
            sA[nbuf][aseg + 1][arow] = aN.y;
            sA[nbuf][aseg + 2][arow] = aN.z;
            sA[nbuf][aseg + 3][arow] = aN.w;
            *(float4*)&sW[nbuf][wrow][wcol] = wN;
            __syncthreads();
        }
    }

    // epilogue
    float4 bv[2];
    #pragma unroll
    for (int jh = 0; jh < 2; jh++) {
        int gn = n0 + jh * 64 + tx4;
        bv[jh] = (gn < N) ? *(const float4*)(bias + gn) : make_float4(0.f, 0.f, 0.f, 0.f);
    }
    #pragma unroll
    for (int ih = 0; ih < 2; ih++) {
        #pragma unroll
        for (int i = 0; i < 4; i++) {
            int gm = m0 + ih * 64 + ty4 + i;
            if (gm >= M) continue;
            int ai = ih * 4 + i;
            #pragma unroll
            for (int jh = 0; jh < 2; jh++) {
                int gn = n0 + jh * 64 + tx4;
                if (gn >= N) continue;
                float4 out;
                out.x = acc[ai][jh * 4 + 0] + bv[jh].x;
                out.y = acc[ai][jh * 4 + 1] + bv[jh].y;
                out.z = acc[ai][jh * 4 + 2] + bv[jh].z;
                out.w = acc[ai][jh * 4 + 3] + bv[jh].w;
                if (RES) {
                    float4 r = *(const float4*)(R + (size_t)gm * N + gn);
                    out.x += r.x; out.y += r.y; out.z += r.z; out.w += r.w;
                }
                if (RELU) {
                    out.x = fmaxf(out.x, 0.f); out.y = fmaxf(out.y, 0.f);
                    out.z = fmaxf(out.z, 0.f); out.w = fmaxf(out.w, 0.f);
                }
                *(float4*)(C + (size_t)gm * N + gn) = out;
            }
        }
    }
}

// ---------------- LayerNorm (warp per token), optional ReLU ----------------
template<int RELU>
__global__ void ln_k(const float* __restrict__ X, const float* __restrict__ g,
                     const float* __restrict__ b, float* __restrict__ Y,
                     int T, int N)
{
    int wid = threadIdx.x >> 5, lane = threadIdx.x & 31;
    int t = blockIdx.x * (blockDim.x >> 5) + wid;
    if (t >= T) return;
    const float* x = X + (size_t)t * N;
    float s = 0.f;
    for (int i = lane; i < N; i += 32) s += x[i];
    #pragma unroll
    for (int o = 16; o; o >>= 1) s += __shfl_xor_sync(~0u, s, o);
    float mean = s / (float)N;
    float v = 0.f;
    for (int i = lane; i < N; i += 32) { float d = x[i] - mean; v = fmaf(d, d, v); }
    #pragma unroll
    for (int o = 16; o; o >>= 1) v += __shfl_xor_sync(~0u, v, o);
    float inv = rsqrtf(v / (float)N + 1e-5f);
    float* y = Y + (size_t)t * N;
    for (int i = lane; i < N; i += 32) {
        float r = (x[i] - mean) * inv * g[i] + b[i];
        if (RELU) r = fmaxf(r, 0.f);
        y[i] = r;
    }
}

// ---------------- padding mask (warp per token) ----------------
__global__ void mask_k(const float* __restrict__ x, float* __restrict__ mask)
{
    int wid = threadIdx.x >> 5, lane = threadIdx.x & 31;
    int token = blockIdx.x * (blockDim.x >> 5) + wid;
    if (token >= T_EMB) return;
    int b = token / L_, l = token % L_;
    const float* row = x + (size_t)token * PD_;
    float m = -3.4e38f;
    for (int i = lane; i < PD_; i += 32) m = fmaxf(m, row[i]);
    #pragma unroll
    for (int o = 16; o; o >>= 1) m = fmaxf(m, __shfl_xor_sync(~0u, m, o));
    if (lane == 0) {
        mask[b * LP_ + 1 + l] = (m == 0.f) ? 1.f : 0.f;
        if (l == 0) mask[b * LP_] = 0.f;   // CLS always valid
    }
}

// ---------------- assemble: h = concat(cls, embed + pos) ----------------
__global__ void assemble_k(const float* __restrict__ t2, const float* __restrict__ pos,
                           const float* __restrict__ cls, float* __restrict__ h)
{
    int idx = blockIdx.x * blockDim.x + threadIdx.x;
    if (idx >= T_ALL * D_) return;
    int d = idx % D_;
    int bt = idx / D_;
    int t = bt % LP_;
    int b = bt / LP_;
    float v;
    if (t == 0) v = cls[d];
    else        v = t2[((size_t)b * L_ + (t - 1)) * D_ + d] + pos[(size_t)(t - 1) * D_ + d];
    h[idx] = v;
}

// ---------------- attention: thread-per-query online softmax ----------------
// qkv: [T_ALL, 720] with q|k|v concatenated.  out: [T_ALL, 240].
__global__ __launch_bounds__(288)
void attn_k(const float* __restrict__ qkv, const float* __restrict__ mask,
            float* __restrict__ o)
{
    const int hh = blockIdx.x;
    const int b  = blockIdx.y;
    __shared__ __align__(16) float sQ[LP_][DKP_];
    __shared__ __align__(16) float sK[LP_][DKP_];
    __shared__ __align__(16) float sV[LP_][DKP_];
    __shared__ float sM[LP_];

    const int tid = threadIdx.x;
    // cooperative stage
    for (int idx = tid; idx < LP_ * DK_; idx += 288) {
        int t = idx / DK_, d = idx % DK_;
        size_t g = (size_t)(b * LP_ + t) * QKVN_ + hh * DK_ + d;
        sQ[t][d] = qkv[g];
        sK[t][d] = qkv[g + D_];
        sV[t][d] = qkv[g + 2 * D_];
    }
    for (int t = tid; t < LP_; t += 288) {
        sQ[t][15] = 0.f; sK[t][15] = 0.f; sV[t][15] = 0.f;
        sM[t] = mask[b * LP_ + t];
    }
    __syncthreads();

    if (tid >= LP_) return;

    float4 q0 = *(const float4*)&sQ[tid][0];
    float4 q1 = *(const float4*)&sQ[tid][4];
    float4 q2 = *(const float4*)&sQ[tid][8];
    float4 q3 = *(const float4*)&sQ[tid][12];

    float m = -3.4e38f, l = 0.f;
    float4 o0 = {0,0,0,0}, o1 = {0,0,0,0}, o2 = {0,0,0,0}, o3 = {0,0,0,0};

    for (int j = 0; j < LP_; j++) {
        float4 k0 = *(const float4*)&sK[j][0];
        float4 k1 = *(const float4*)&sK[j][4];
        float4 k2 = *(const float4*)&sK[j][8];
        float4 k3 = *(const float4*)&sK[j][12];
        float s = q0.x*k0.x + q0.y*k0.y + q0.z*k0.z + q0.w*k0.w
                + q1.x*k1.x + q1.y*k1.y + q1.z*k1.z + q1.w*k1.w
                + q2.x*k2.x + q2.y*k2.y + q2.z*k2.z + q2.w*k2.w
                + q3.x*k3.x + q3.y*k3.y + q3.z*k3.z;
        s = (sM[j] != 0.f) ? -10000.f : s * SCALE_;

        if (s > m) {
            float f = __expf(m - s);
            m = s;
            l *= f;
            o0.x *= f; o0.y *= f; o0.z *= f; o0.w *= f;
            o1.x *= f; o1.y *= f; o1.z *= f; o1.w *= f;
            o2.x *= f; o2.y *= f; o2.z *= f; o2.w *= f;
            o3.x *= f; o3.y *= f; o3.z *= f; o3.w *= f;
        }
        float p = __expf(s - m);
        l += p;
        float4 v0 = *(const float4*)&sV[j][0];
        float4 v1 = *(const float4*)&sV[j][4];
        float4 v2 = *(const float4*)&sV[j][8];
        float4 v3 = *(const float4*)&sV[j][12];
        o0.x = fmaf(p, v0.x, o0.x); o0.y = fmaf(p, v0.y, o0.y);
        o0.z = fmaf(p, v0.z, o0.z); o0.w = fmaf(p, v0.w, o0.w);
        o1.x = fmaf(p, v1.x, o1.x); o1.y = fmaf(p, v1.y, o1.y);
        o1.z = fmaf(p, v1.z, o1.z); o1.w = fmaf(p, v1.w, o1.w);
        o2.x = fmaf(p, v2.x, o2.x); o2.y = fmaf(p, v2.y, o2.y);
        o2.z = fmaf(p, v2.z, o2.z); o2.w = fmaf(p, v2.w, o2.w);
        o3.x = fmaf(p, v3.x, o3.x); o3.y = fmaf(p, v3.y, o3.y);
        o3.z = fmaf(p, v3.z, o3.z);
    }
    float inv = 1.f / l;
    float* op = o + (size_t)(b * LP_ + tid) * D_ + hh * DK_;
    op[0]  = o0.x * inv; op[1]  = o0.y * inv; op[2]  = o0.z * inv; op[3]  = o0.w * inv;
    op[4]  = o1.x * inv; op[5]  = o1.y * inv; op[6]  = o1.z * inv; op[7]  = o1.w * inv;
    op[8]  = o2.x * inv; op[9]  = o2.y * inv; op[10] = o2.z * inv; op[11] = o2.w * inv;
    op[12] = o3.x * inv; op[13] = o3.y * inv; op[14] = o3.z * inv;
}

// ---------------- masked mean pool + logits (block per batch) ----------------
__global__ __launch_bounds__(256)
void pool_k(const float* __restrict__ h, const float* __restrict__ mask,
            const float* __restrict__ lw, const float* __restrict__ lb,
            float* __restrict__ out)
{
    int b = blockIdx.x;
    __shared__ float sp[D_];
    __shared__ float sm[LP_];
    int tid = threadIdx.x;
    for (int t = tid; t < LP_; t += blockDim.x) sm[t] = mask[b * LP_ + t];
    __syncthreads();
    float cnt = 0.f;
    for (int t = 0; t < LP_; t++) cnt += 1.f - sm[t];
    if (tid < D_) {
        float acc = 0.f;
        for (int t = 0; t < LP_; t++) {
            float w = 1.f - sm[t];
            acc = fmaf(h[((size_t)b * LP_ + t) * D_ + tid], w, acc);
        }
        sp[tid] = acc / cnt;
    }
    __syncthreads();
    if (tid < NC_) {
        float acc = lb[tid];
        for (int d = 0; d < D_; d++) acc = fmaf(sp[d], lw[(size_t)d * NC_ + tid], acc);
        out[b * NC_ + tid] = acc;
    }
}

// ---------------- host launch ----------------
static inline void launch_gemm(const float* A, const float* W, const float* bias,
                               const float* R, float* C, int M, int N, int K,
                               int relu, int res)
{
    dim3 grid((N + GBN - 1) / GBN, (M + GBM - 1) / GBM);
    if (res)       gemm_k<0,1><<<grid, 256>>>(A, W, bias, R, C, M, N, K);
    else if (relu) gemm_k<1,0><<<grid, 256>>>(A, W, bias, R, C, M, N, K);
    else           gemm_k<0,0><<<grid, 256>>>(A, W, bias, R, C, M, N, K);
}

extern "C" void kernel_launch(void* const* d_in, const int* in_sizes, int n_in,
                              void* d_out, int out_size)
{
    const float* x       = (const float*)d_in[0];
    const float* pos     = (const float*)d_in[1];
    const float* cls     = (const float*)d_in[2];
    const float* e_W1    = (const float*)d_in[3];
    const float* e_b1    = (const float*)d_in[4];
    const float* e_g1    = (const float*)d_in[5];
    const float* e_bn1   = (const float*)d_in[6];
    const float* e_W2    = (const float*)d_in[7];
    const float* e_b2    = (const float*)d_in[8];
    const float* e_g2    = (const float*)d_in[9];
    const float* e_bn2   = (const float*)d_in[10];
    const float* ln1_g   = (const float*)d_in[11];
    const float* ln1_b   = (const float*)d_in[12];
    const float* Wq      = (const float*)d_in[13];
    const float* bq      = (const float*)d_in[14];
    const float* Wk      = (const float*)d_in[15];
    const float* bk      = (const float*)d_in[16];
    const float* Wv      = (const float*)d_in[17];
    const float* bv      = (const float*)d_in[18];
    const float* Wo      = (const float*)d_in[19];
    const float* bo      = (const float*)d_in[20];
    const float* ln2_g   = (const float*)d_in[21];
    const float* ln2_b   = (const float*)d_in[22];
    const float* W1      = (const float*)d_in[23];
    const float* b1      = (const float*)d_in[24];
    const float* W2      = (const float*)d_in[25];
    const float* b2      = (const float*)d_in[26];
    const float* logit_W = (const float*)d_in[27];
    const float* logit_b = (const float*)d_in[28];
    float* out = (float*)d_out;

    float *h, *y, *qkv, *o, *f, *msk, *wqkv, *bqkv;
    cudaGetSymbolAddress((void**)&h,    g_h);
    cudaGetSymbolAddress((void**)&y,    g_y);
    cudaGetSymbolAddress((void**)&qkv,  g_qkv);
    cudaGetSymbolAddress((void**)&o,    g_o);
    cudaGetSymbolAddress((void**)&f,    g_f);
    cudaGetSymbolAddress((void**)&msk,  g_mask);
    cudaGetSymbolAddress((void**)&wqkv, g_wqkv);
    cudaGetSymbolAddress((void**)&bqkv, g_bqkv);

    // ---- pack QKV weights + padding mask ----
    packqkv_k<<<(NB_ * D_ * QKVN_ + 255) / 256, 256>>>(Wq, Wk, Wv, bq, bk, bv, wqkv, bqkv);
    mask_k<<<(T_EMB + 7) / 8, 256>>>(x, msk);

    // ---- XEmbed ----
    launch_gemm(x, e_W1, e_b1, nullptr, f, T_EMB, HID_, PD_, 0, 0);
    ln_k<1><<<(T_EMB + 7) / 8, 256>>>(f, e_g1, e_bn1, f, T_EMB, HID_);
    launch_gemm(f, e_W2, e_b2, nullptr, y, T_EMB, D_, HID_, 0, 0);
    ln_k<1><<<(T_EMB + 7) / 8, 256>>>(y, e_g2, e_bn2, y, T_EMB, D_);
    assemble_k<<<(T_ALL * D_ + 255) / 256, 256>>>(y, pos, cls, h);

    // ---- transformer blocks ----
    for (int i = 0; i < NB_; i++) {
        ln_k<0><<<(T_ALL + 7) / 8, 256>>>(h, ln1_g + i * D_, ln1_b + i * D_, y, T_ALL, D_);
        launch_gemm(y, wqkv + (size_t)i * D_ * QKVN_, bqkv + i * QKVN_, nullptr,
                    qkv, T_ALL, QKVN_, D_, 0, 0);
        attn_k<<<dim3(H_, B_), 288>>>(qkv, msk, o);
        launch_gemm(o, Wo + (size_t)i * D_ * D_, bo + i * D_, h, h, T_ALL, D_, D_, 0, 1);
        ln_k<0><<<(T_ALL + 7) / 8, 256>>>(h, ln2_g + i * D_, ln2_b + i * D_, y, T_ALL, D_);
        launch_gemm(y, W1 + (size_t)i * D_ * HID_, b1 + i * HID_, nullptr, f, T_ALL, HID_, D_, 1, 0);
        launch_gemm(f, W2 + (size_t)i * HID_ * D_, b2 + i * D_, h, h, T_ALL, D_, HID_, 0, 1);
    }

    // ---- pool + logits ----
    pool_k<<<B_, 256>>>(h, msk, logit_W, logit_b, out);
}

// round 15
// speedup vs baseline: 1.8872x; 1.4112x over previous
#include <cuda_runtime.h>
#include <cuda_bf16.h>
#include <math.h>
#include <stdint.h>

// ---------------- problem constants ----------------
#define B_    32
#define L_    256
#define PD_   164
#define D_    240
#define H_    16
#define NB_   6
#define NC_   250
#define DK_   15
#define HID_  480
#define LP_   257
#define T_EMB (B_*L_)      // 8192
#define T_ALL (B_*LP_)     // 8224
#define MPAD_ 8320         // 65*128
#define SCALE_ 0.25819888974716115f
#define QKVN_ 720

// ---------------- scratch (device globals; zero-initialized at load) ----------------
__device__ float g_h   [T_ALL * D_];
__device__ float g_y   [T_EMB * D_];
__device__ float g_qkv [T_ALL * QKVN_];
__device__ float g_f   [T_EMB * HID_];
__device__ float g_mask[T_ALL];
__device__ float g_bqkv[NB_ * 768];

// bf16 split activation buffers (padded rows)
__device__ __nv_bfloat16 g_ah[MPAD_ * 512], g_al[MPAD_ * 512];
__device__ __nv_bfloat16 g_fh[MPAD_ * 512], g_fl[MPAD_ * 512];

// bf16 split transposed weights  Wt[l][Npad][Kpad]
__device__ __nv_bfloat16 g_weh1[512*192], g_wel1[512*192];
__device__ __nv_bfloat16 g_weh2[256*512], g_wel2[256*512];
__device__ __nv_bfloat16 g_wqh [NB_*768*256], g_wql [NB_*768*256];
__device__ __nv_bfloat16 g_woh [NB_*256*256], g_wol [NB_*256*256];
__device__ __nv_bfloat16 g_w1h [NB_*512*256], g_w1l [NB_*512*256];
__device__ __nv_bfloat16 g_w2h [NB_*256*512], g_w2l [NB_*256*512];

// ---------------- helpers ----------------
__device__ __forceinline__ uint32_t smem_u32(const void* p) {
    return (uint32_t)__cvta_generic_to_shared(p);
}
__device__ __forceinline__ void split_bf16(float v, __nv_bfloat16& hi, __nv_bfloat16& lo) {
    hi = __float2bfloat16(v);
    lo = __float2bfloat16(v - __bfloat162float(hi));
}
__device__ __forceinline__ void cp16(uint32_t dst, const void* src) {
    asm volatile("cp.async.cg.shared.global [%0], [%1], 16;"
                 :: "r"(dst), "l"(src) : "memory");
}
__device__ __forceinline__ void cp_commit() {
    asm volatile("cp.async.commit_group;" ::: "memory");
}
template<int N> __device__ __forceinline__ void cp_wait() {
    asm volatile("cp.async.wait_group %0;" :: "n"(N) : "memory");
}
__device__ __forceinline__ void ldm4(uint32_t* r, uint32_t addr) {
    asm volatile("ldmatrix.sync.aligned.m8n8.x4.shared.b16 {%0,%1,%2,%3}, [%4];"
                 : "=r"(r[0]), "=r"(r[1]), "=r"(r[2]), "=r"(r[3]) : "r"(addr));
}
__device__ __forceinline__ void mma_bf16(float* c, const uint32_t* a,
                                         uint32_t b0, uint32_t b1) {
    asm volatile(
        "mma.sync.aligned.m16n8k16.row.col.f32.bf16.bf16.f32 "
        "{%0,%1,%2,%3}, {%4,%5,%6,%7}, {%8,%9}, {%0,%1,%2,%3};"
        : "+f"(c[0]), "+f"(c[1]), "+f"(c[2]), "+f"(c[3])
        : "r"(a[0]), "r"(a[1]), "r"(a[2]), "r"(a[3]), "r"(b0), "r"(b1));
}

// ---------------- mma.sync GEMM: 128x128 tile, split-bf16 fp32 emulation ----------
// A (hi/lo): [rows][Kpad] bf16.  B (hi/lo): [Npad][Kpad] bf16 (weights transposed).
// D = Ahi*Bhi + Ahi*Blo + Alo*Bhi (fp32 register accum).
// SPLIT=0: Cf[gm*ldc+gn] = acc + bias (+R) (relu), gm<M, gn<N (ldc==N or >).
// SPLIT=1: Ch/Cl bf16 at ld ldc; value 0 for gn in [N,ldc).
#define TILE_B 16384
#define BUF_B  65536
#define SMEM_MMA_BYTES 131072

template<int SPLIT, int RES, int RELU>
__global__ __launch_bounds__(256)
void gemm_mma_k(const __nv_bfloat16* __restrict__ Ah, const __nv_bfloat16* __restrict__ Al,
                const __nv_bfloat16* __restrict__ Bh, const __nv_bfloat16* __restrict__ Bl,
                int Kpad,
                const float* __restrict__ bias, const float* __restrict__ R,
                float* __restrict__ Cf, __nv_bfloat16* __restrict__ Ch,
                __nv_bfloat16* __restrict__ Cl,
                int ldc, int M, int N)
{
    extern __shared__ char sm[];
    const int tid  = threadIdx.x;
    const int lane = tid & 31;
    const int wid  = tid >> 5;
    const int wm   = wid >> 1;   // 0..3  -> m offset wm*32
    const int wn   = wid & 1;    // 0..1  -> n offset wn*64
    const int n0   = blockIdx.x * 128;
    const int m0   = blockIdx.y * 128;
    const uint32_t smb = smem_u32(sm);

    // ---- staging mapping: thread handles row r, half of its 128B chunk ----
    const int r    = tid >> 1;
    const int half = tid & 1;
    const uint32_t st_rb = (uint32_t)r * 128u;
    const uint32_t st_rx = (uint32_t)((r & 7) << 4);
    const uint32_t st_cx = (uint32_t)(half * 64);

    const __nv_bfloat16* gsrc[4] = {
        Ah + (size_t)m0 * Kpad, Al + (size_t)m0 * Kpad,
        Bh + (size_t)n0 * Kpad, Bl + (size_t)n0 * Kpad };
    const uint32_t soff[4] = { 0u, 16384u, 32768u, 49152u };

    const int KC = Kpad >> 6;

    // ---- fragment address precompute ----
    const uint32_t rxor = (uint32_t)((lane & 7) << 4);
    uint32_t aro[2], bro[4];
    #pragma unroll
    for (int mt = 0; mt < 2; mt++)
        aro[mt] = (uint32_t)(wm * 32 + mt * 16 + (lane & 15)) * 128u;
    #pragma unroll
    for (int nq = 0; nq < 4; nq++)
        bro[nq] = (uint32_t)(wn * 64 + nq * 16 + ((lane >> 4) << 3) + (lane & 7)) * 128u;
    const uint32_t kbA = (uint32_t)(((lane >> 4) & 1) * 16);
    const uint32_t kbB = (uint32_t)(((lane >> 3) & 1) * 16);

    float acc[2][8][4];
    #pragma unroll
    for (int mt = 0; mt < 2; mt++)
        #pragma unroll
        for (int nt = 0; nt < 8; nt++)
            #pragma unroll
            for (int e = 0; e < 4; e++) acc[mt][nt][e] = 0.f;

    // ---- prologue: stage chunk 0 ----
    {
        const size_t gofs = (size_t)r * Kpad + half * 32;
        #pragma unroll
        for (int t = 0; t < 4; t++) {
            const __nv_bfloat16* s = gsrc[t] + gofs;
            uint32_t db = smb + soff[t] + st_rb;
            #pragma unroll
            for (int i = 0; i < 4; i++)
                cp16(db + ((st_cx + i * 16) ^ st_rx), s + i * 8);
        }
        cp_commit();
    }

    for (int c = 0; c < KC; c++) {
        if (c + 1 < KC) {
            const uint32_t bo = (uint32_t)((c + 1) & 1) * BUF_B;
            const size_t gofs = (size_t)r * Kpad + (size_t)(c + 1) * 64 + half * 32;
            #pragma unroll
            for (int t = 0; t < 4; t++) {
                const __nv_bfloat16* s = gsrc[t] + gofs;
                uint32_t db = smb + bo + soff[t] + st_rb;
                #pragma unroll
                for (int i = 0; i < 4; i++)
                    cp16(db + ((st_cx + i * 16) ^ st_rx), s + i * 8);
            }
            cp_commit();
            cp_wait<1>();
        } else {
            cp_wait<0>();
        }
        __syncthreads();

        const uint32_t bo = (uint32_t)(c & 1) * BUF_B;
        const uint32_t sah = smb + bo;
        const uint32_t sal = smb + bo + 16384u;
        const uint32_t sbh = smb + bo + 32768u;
        const uint32_t sbl = smb + bo + 49152u;

        #pragma unroll
        for (int ks = 0; ks < 4; ks++) {
            const uint32_t colA = ((uint32_t)(ks * 32) + kbA) ^ rxor;
            const uint32_t colB = ((uint32_t)(ks * 32) + kbB) ^ rxor;
            uint32_t ah[2][4], al[2][4], bh[4][4], bl[4][4];
            #pragma unroll
            for (int mt = 0; mt < 2; mt++) {
                ldm4(ah[mt], sah + aro[mt] + colA);
                ldm4(al[mt], sal + aro[mt] + colA);
            }
            #pragma unroll
            for (int nq = 0; nq < 4; nq++) {
                ldm4(bh[nq], sbh + bro[nq] + colB);
                ldm4(bl[nq], sbl + bro[nq] + colB);
            }
            #pragma unroll
            for (int mt = 0; mt < 2; mt++) {
                #pragma unroll
                for (int nt = 0; nt < 8; nt++) {
                    const int nq = nt >> 1;
                    const int p  = (nt & 1) * 2;   // frag regs {p, p+1}
                    mma_bf16(acc[mt][nt], ah[mt], bh[nq][p], bh[nq][p + 1]);
                    mma_bf16(acc[mt][nt], ah[mt], bl[nq][p], bl[nq][p + 1]);
                    mma_bf16(acc[mt][nt], al[mt], bh[nq][p], bh[nq][p + 1]);
                }
            }
        }
        __syncthreads();
    }

    // ---- epilogue: fragment layout c0,c1 @ (row, col..col+1); c2,c3 @ (row+8, ..) --
    const int qr = lane >> 2, qc = lane & 3;
    #pragma unroll
    for (int mt = 0; mt < 2; mt++) {
        const int rbase = m0 + wm * 32 + mt * 16 + qr;
        #pragma unroll
        for (int nt = 0; nt < 8; nt++) {
            const int col = n0 + wn * 64 + nt * 8 + qc * 2;
            const float* a4 = acc[mt][nt];
            if (!SPLIT) {
                if (col >= N) continue;
                const float2 bv = *(const float2*)(bias + col);
                #pragma unroll
                for (int hrow = 0; hrow < 2; hrow++) {
                    const int gm = rbase + hrow * 8;
                    if (gm >= M) continue;
                    float2 o;
                    o.x = a4[hrow * 2 + 0] + bv.x;
                    o.y = a4[hrow * 2 + 1] + bv.y;
                    if (RES) {
                        const float2 rr = *(const float2*)(R + (size_t)gm * ldc + col);
                        o.x += rr.x; o.y += rr.y;
                    }
                    if (RELU) { o.x = fmaxf(o.x, 0.f); o.y = fmaxf(o.y, 0.f); }
                    *(float2*)(Cf + (size_t)gm * ldc + col) = o;
                }
            } else {
                #pragma unroll
                for (int hrow = 0; hrow < 2; hrow++) {
                    const int gm = rbase + hrow * 8;
                    if (gm >= M) continue;
                    float v0 = 0.f, v1 = 0.f;
                    if (col < N)     v0 = a4[hrow * 2 + 0] + bias[col];
                    if (col + 1 < N) v1 = a4[hrow * 2 + 1] + bias[col + 1];
                    if (RELU) { v0 = fmaxf(v0, 0.f); v1 = fmaxf(v1, 0.f); }
                    __nv_bfloat162 h2, l2;
                    __nv_bfloat16 hh, ll;
                    split_bf16(v0, hh, ll); h2.x = hh; l2.x = ll;
                    split_bf16(v1, hh, ll); h2.y = hh; l2.y = ll;
                    *(__nv_bfloat162*)(Ch + (size_t)gm * ldc + col) = h2;
                    *(__nv_bfloat162*)(Cl + (size_t)gm * ldc + col) = l2;
                }
            }
        }
    }
}

// ---------------- weight split/transpose: W[l][K][N] -> Wt[l][Npad][Kpad] hi/lo ----
__global__ void wsplit_k(const float* __restrict__ W, int K, int N, int Kpad, int Npad,
                         int nmat, int wstride,
                         __nv_bfloat16* __restrict__ oh, __nv_bfloat16* __restrict__ ol)
{
    int idx = blockIdx.x * blockDim.x + threadIdx.x;
    int total = nmat * Npad * Kpad;
    if (idx >= total) return;
    int k = idx % Kpad;
    int n = (idx / Kpad) % Npad;
    int l = idx / (Kpad * Npad);
    float v = (k < K && n < N) ? W[(size_t)l * wstride + (size_t)k * N + n] : 0.f;
    __nv_bfloat16 hi, lo; split_bf16(v, hi, lo);
    oh[idx] = hi; ol[idx] = lo;
}

__global__ void qkvsplit_k(const float* __restrict__ Wq, const float* __restrict__ Wk,
                           const float* __restrict__ Wv,
                           __nv_bfloat16* __restrict__ oh, __nv_bfloat16* __restrict__ ol)
{
    int idx = blockIdx.x * blockDim.x + threadIdx.x;
    const int total = NB_ * 768 * 256;
    if (idx >= total) return;
    int k = idx & 255;
    int n = (idx >> 8) % 768;
    int l = idx / (256 * 768);
    float v = 0.f;
    if (k < D_ && n < 720) {
        const float* src = (n < 240) ? Wq : ((n < 480) ? Wk : Wv);
        v = src[(size_t)l * D_ * D_ + (size_t)k * D_ + (n % 240)];
    }
    __nv_bfloat16 hi, lo; split_bf16(v, hi, lo);
    oh[idx] = hi; ol[idx] = lo;
}

__global__ void bpackqkv_k(const float* __restrict__ bq, const float* __restrict__ bk,
                           const float* __restrict__ bv, float* __restrict__ o)
{
    int idx = blockIdx.x * blockDim.x + threadIdx.x;
    if (idx >= NB_ * 768) return;
    int c = idx % 768, l = idx / 768;
    float v = 0.f;
    if (c < 720) {
        const float* src = (c < 240) ? bq : ((c < 480) ? bk : bv);
        v = src[l * D_ + (c % 240)];
    }
    o[idx] = v;
}

// ---------------- x -> split bf16 (ld 192, zero pad) ----------------
__global__ void convx_k(const float* __restrict__ x,
                        __nv_bfloat16* __restrict__ oh, __nv_bfloat16* __restrict__ ol)
{
    int idx = blockIdx.x * blockDim.x + threadIdx.x;
    const int total = T_EMB * 192;
    if (idx >= total) return;
    int k = idx % 192, t = idx / 192;
    float v = (k < PD_) ? x[(size_t)t * PD_ + k] : 0.f;
    __nv_bfloat16 hi, lo; split_bf16(v, hi, lo);
    oh[idx] = hi; ol[idx] = lo;
}

// ---------------- LayerNorm fp32 -> split bf16 (warp per token) ----------------
template<int RELU>
__global__ void ln_split_k(const float* __restrict__ X, const float* __restrict__ g,
                           const float* __restrict__ b,
                           __nv_bfloat16* __restrict__ Yh, __nv_bfloat16* __restrict__ Yl,
                           int T, int N, int LDO)
{
    int wid = threadIdx.x >> 5, lane = threadIdx.x & 31;
    int t = blockIdx.x * (blockDim.x >> 5) + wid;
    if (t >= T) return;
    const float* x = X + (size_t)t * N;
    float s = 0.f;
    for (int i = lane; i < N; i += 32) s += x[i];
    #pragma unroll
    for (int o = 16; o; o >>= 1) s += __shfl_xor_sync(~0u, s, o);
    float mean = s / (float)N;
    float v = 0.f;
    for (int i = lane; i < N; i += 32) { float d = x[i] - mean; v = fmaf(d, d, v); }
    #pragma unroll
    for (int o = 16; o; o >>= 1) v += __shfl_xor_sync(~0u, v, o);
    float inv = rsqrtf(v / (float)N + 1e-5f);
    __nv_bfloat16* yh = Yh + (size_t)t * LDO;
    __nv_bfloat16* yl = Yl + (size_t)t * LDO;
    for (int i = lane; i < LDO; i += 32) {
        float r = 0.f;
        if (i < N) {
            r = (x[i] - mean) * inv * g[i] + b[i];
            if (RELU) r = fmaxf(r, 0.f);
        }
        __nv_bfloat16 hi, lo; split_bf16(r, hi, lo);
        yh[i] = hi; yl[i] = lo;
    }
}

// ---------------- LayerNorm fp32 -> fp32 (+relu) ----------------
template<int RELU>
__global__ void ln_k(const float* __restrict__ X, const float* __restrict__ g,
                     const float* __restrict__ b, float* __restrict__ Y, int T, int N)
{
    int wid = threadIdx.x >> 5, lane = threadIdx.x & 31;
    int t = blockIdx.x * (blockDim.x >> 5) + wid;
    if (t >= T) return;
    const float* x = X + (size_t)t * N;
    float s = 0.f;
    for (int i = lane; i < N; i += 32) s += x[i];
    #pragma unroll
    for (int o = 16; o; o >>= 1) s += __shfl_xor_sync(~0u, s, o);
    float mean = s / (float)N;
    float v = 0.f;
    for (int i = lane; i < N; i += 32) { float d = x[i] - mean; v = fmaf(d, d, v); }
    #pragma unroll
    for (int o = 16; o; o >>= 1) v += __shfl_xor_sync(~0u, v, o);
    float inv = rsqrtf(v / (float)N + 1e-5f);
    float* y = Y + (size_t)t * N;
    for (int i = lane; i < N; i += 32) {
        float r = (x[i] - mean) * inv * g[i] + b[i];
        if (RELU) r = fmaxf(r, 0.f);
        y[i] = r;
    }
}

// ---------------- padding mask ----------------
__global__ void mask_k(const float* __restrict__ x, float* __restrict__ mask)
{
    int wid = threadIdx.x >> 5, lane = threadIdx.x & 31;
    int token = blockIdx.x * (blockDim.x >> 5) + wid;
    if (token >= T_EMB) return;
    int b = token / L_, l = token % L_;
    const float* row = x + (size_t)token * PD_;
    float m = -3.4e38f;
    for (int i = lane; i < PD_; i += 32) m = fmaxf(m, row[i]);
    #pragma unroll
    for (int o = 16; o; o >>= 1) m = fmaxf(m, __shfl_xor_sync(~0u, m, o));
    if (lane == 0) {
        mask[b * LP_ + 1 + l] = (m == 0.f) ? 1.f : 0.f;
        if (l == 0) mask[b * LP_] = 0.f;
    }
}

// ---------------- assemble ----------------
__global__ void assemble_k(const float* __restrict__ t2, const float* __restrict__ pos,
                           const float* __restrict__ cls, float* __restrict__ h)
{
    int idx = blockIdx.x * blockDim.x + threadIdx.x;
    if (idx >= T_ALL * D_) return;
    int d = idx % D_;
    int bt = idx / D_;
    int t = bt % LP_;
    int b = bt / LP_;
    float v;
    if (t == 0) v = cls[d];
    else        v = t2[((size_t)b * L_ + (t - 1)) * D_ + d] + pos[(size_t)(t - 1) * D_ + d];
    h[idx] = v;
}

// ---------------- attention: thread-per-query online softmax, split-bf16 output ----
__global__ __launch_bounds__(288)
void attn_k(const float* __restrict__ qkv, const float* __restrict__ mask,
            __nv_bfloat16* __restrict__ Oh, __nv_bfloat16* __restrict__ Ol)
{
    const int hh = blockIdx.x;
    const int b  = blockIdx.y;
    __shared__ __align__(16) float sQ[LP_][16];
    __shared__ __align__(16) float sK[LP_][16];
    __shared__ __align__(16) float sV[LP_][16];
    __shared__ float sM[LP_];

    const int tid = threadIdx.x;
    for (int idx = tid; idx < LP_ * DK_; idx += 288) {
        int t = idx / DK_, d = idx % DK_;
        size_t g = (size_t)(b * LP_ + t) * QKVN_ + hh * DK_ + d;
        sQ[t][d] = qkv[g];
        sK[t][d] = qkv[g + D_];
        sV[t][d] = qkv[g + 2 * D_];
    }
    for (int t = tid; t < LP_; t += 288) {
        sQ[t][15] = 0.f; sK[t][15] = 0.f; sV[t][15] = 0.f;
        sM[t] = mask[b * LP_ + t];
    }
    __syncthreads();

    if (tid >= LP_) return;

    float4 q0 = *(const float4*)&sQ[tid][0];
    float4 q1 = *(const float4*)&sQ[tid][4];
    float4 q2 = *(const float4*)&sQ[tid][8];
    float4 q3 = *(const float4*)&sQ[tid][12];

    float m = -3.4e38f, l = 0.f;
    float4 o0 = {0,0,0,0}, o1 = {0,0,0,0}, o2 = {0,0,0,0}, o3 = {0,0,0,0};

    for (int j = 0; j < LP_; j++) {
        float4 k0 = *(const float4*)&sK[j][0];
        float4 k1 = *(const float4*)&sK[j][4];
        float4 k2 = *(const float4*)&sK[j][8];
        float4 k3 = *(const float4*)&sK[j][12];
        float s = q0.x*k0.x + q0.y*k0.y + q0.z*k0.z + q0.w*k0.w
                + q1.x*k1.x + q1.y*k1.y + q1.z*k1.z + q1.w*k1.w
                + q2.x*k2.x + q2.y*k2.y + q2.z*k2.z + q2.w*k2.w
                + q3.x*k3.x + q3.y*k3.y + q3.z*k3.z;
        s = (sM[j] != 0.f) ? -10000.f : s * SCALE_;
        if (s > m) {
            float f = __expf(m - s);
            m = s; l *= f;
            o0.x *= f; o0.y *= f; o0.z *= f; o0.w *= f;
            o1.x *= f; o1.y *= f; o1.z *= f; o1.w *= f;
            o2.x *= f; o2.y *= f; o2.z *= f; o2.w *= f;
            o3.x *= f; o3.y *= f; o3.z *= f; o3.w *= f;
        }
        float p = __expf(s - m);
        l += p;
        float4 v0 = *(const float4*)&sV[j][0];
        float4 v1 = *(const float4*)&sV[j][4];
        float4 v2 = *(const float4*)&sV[j][8];
        float4 v3 = *(const float4*)&sV[j][12];
        o0.x = fmaf(p, v0.x, o0.x); o0.y = fmaf(p, v0.y, o0.y);
        o0.z = fmaf(p, v0.z, o0.z); o0.w = fmaf(p, v0.w, o0.w);
        o1.x = fmaf(p, v1.x, o1.x); o1.y = fmaf(p, v1.y, o1.y);
        o1.z = fmaf(p, v1.z, o1.z); o1.w = fmaf(p, v1.w, o1.w);
        o2.x = fmaf(p, v2.x, o2.x); o2.y = fmaf(p, v2.y, o2.y);
        o2.z = fmaf(p, v2.z, o2.z); o2.w = fmaf(p, v2.w, o2.w);
        o3.x = fmaf(p, v3.x, o3.x); o3.y = fmaf(p, v3.y, o3.y);
        o3.z = fmaf(p, v3.z, o3.z);
    }
    float inv = 1.f / l;
    float vals[15] = { o0.x, o0.y, o0.z, o0.w, o1.x, o1.y, o1.z, o1.w,
                       o2.x, o2.y, o2.z, o2.w, o3.x, o3.y, o3.z };
    size_t base = (size_t)(b * LP_ + tid) * 256 + hh * DK_;
    #pragma unroll
    for (int d = 0; d < 15; d++) {
        __nv_bfloat16 hi, lo; split_bf16(vals[d] * inv, hi, lo);
        Oh[base + d] = hi; Ol[base + d] = lo;
    }
}

// ---------------- masked mean pool + logits ----------------
__global__ __launch_bounds__(256)
void pool_k(const float* __restrict__ h, const float* __restrict__ mask,
            const float* __restrict__ lw, const float* __restrict__ lb,
            float* __restrict__ out)
{
    int b = blockIdx.x;
    __shared__ float sp[D_];
    __shared__ float smm[LP_];
    int tid = threadIdx.x;
    for (int t = tid; t < LP_; t += blockDim.x) smm[t] = mask[b * LP_ + t];
    __syncthreads();
    float cnt = 0.f;
    for (int t = 0; t < LP_; t++) cnt += 1.f - smm[t];
    if (tid < D_) {
        float acc = 0.f;
        for (int t = 0; t < LP_; t++) {
            float w = 1.f - smm[t];
            acc = fmaf(h[((size_t)b * LP_ + t) * D_ + tid], w, acc);
        }
        sp[tid] = acc / cnt;
    }
    __syncthreads();
    if (tid < NC_) {
        float acc = lb[tid];
        for (int d = 0; d < D_; d++) acc = fmaf(sp[d], lw[(size_t)d * NC_ + tid], acc);
        out[b * NC_ + tid] = acc;
    }
}

// ---------------- host ----------------
extern "C" void kernel_launch(void* const* d_in, const int* in_sizes, int n_in,
                              void* d_out, int out_size)
{
    const float* x       = (const float*)d_in[0];
    const float* pos     = (const float*)d_in[1];
    const float* cls     = (const float*)d_in[2];
    const float* e_W1    = (const float*)d_in[3];
    const float* e_b1    = (const float*)d_in[4];
    const float* e_g1    = (const float*)d_in[5];
    const float* e_bn1   = (const float*)d_in[6];
    const float* e_W2    = (const float*)d_in[7];
    const float* e_b2    = (const float*)d_in[8];
    const float* e_g2    = (const float*)d_in[9];
    const float* e_bn2   = (const float*)d_in[10];
    const float* ln1_g   = (const float*)d_in[11];
    const float* ln1_b   = (const float*)d_in[12];
    const float* Wq      = (const float*)d_in[13];
    const float* bq      = (const float*)d_in[14];
    const float* Wk      = (const float*)d_in[15];
    const float* bk      = (const float*)d_in[16];
    const float* Wv      = (const float*)d_in[17];
    const float* bv      = (const float*)d_in[18];
    const float* Wo      = (const float*)d_in[19];
    const float* bo      = (const float*)d_in[20];
    const float* ln2_g   = (const float*)d_in[21];
    const float* ln2_b   = (const float*)d_in[22];
    const float* W1      = (const float*)d_in[23];
    const float* b1      = (const float*)d_in[24];
    const float* W2      = (const float*)d_in[25];
    const float* b2      = (const float*)d_in[26];
    const float* logit_W = (const float*)d_in[27];
    const float* logit_b = (const float*)d_in[28];
    float* out = (float*)d_out;

    float *h, *y, *qkv, *f, *msk, *bqkv;
    __nv_bfloat16 *ah, *al, *fh, *fl;
    __nv_bfloat16 *weh1, *wel1, *weh2, *wel2, *wqh, *wql, *woh, *wol, *w1h, *w1l, *w2h, *w2l;
    cudaGetSymbolAddress((void**)&h,    g_h);
    cudaGetSymbolAddress((void**)&y,    g_y);
    cudaGetSymbolAddress((void**)&qkv,  g_qkv);
    cudaGetSymbolAddress((void**)&f,    g_f);
    cudaGetSymbolAddress((void**)&msk,  g_mask);
    cudaGetSymbolAddress((void**)&bqkv, g_bqkv);
    cudaGetSymbolAddress((void**)&ah,   g_ah);
    cudaGetSymbolAddress((void**)&al,   g_al);
    cudaGetSymbolAddress((void**)&fh,   g_fh);
    cudaGetSymbolAddress((void**)&fl,   g_fl);
    cudaGetSymbolAddress((void**)&weh1, g_weh1);
    cudaGetSymbolAddress((void**)&wel1, g_wel1);
    cudaGetSymbolAddress((void**)&weh2, g_weh2);
    cudaGetSymbolAddress((void**)&wel2, g_wel2);
    cudaGetSymbolAddress((void**)&wqh,  g_wqh);
    cudaGetSymbolAddress((void**)&wql,  g_wql);
    cudaGetSymbolAddress((void**)&woh,  g_woh);
    cudaGetSymbolAddress((void**)&wol,  g_wol);
    cudaGetSymbolAddress((void**)&w1h,  g_w1h);
    cudaGetSymbolAddress((void**)&w1l,  g_w1l);
    cudaGetSymbolAddress((void**)&w2h,  g_w2h);
    cudaGetSymbolAddress((void**)&w2l,  g_w2l);

    cudaFuncSetAttribute(gemm_mma_k<0,0,0>, cudaFuncAttributeMaxDynamicSharedMemorySize, SMEM_MMA_BYTES);
    cudaFuncSetAttribute(gemm_mma_k<0,1,0>, cudaFuncAttributeMaxDynamicSharedMemorySize, SMEM_MMA_BYTES);
    cudaFuncSetAttribute(gemm_mma_k<1,0,1>, cudaFuncAttributeMaxDynamicSharedMemorySize, SMEM_MMA_BYTES);

    // ---- weight conversion (per call; weights are inputs) ----
    wsplit_k<<<(1*512*192 + 255)/256, 256>>>(e_W1, PD_, HID_, 192, 512, 1, 0, weh1, wel1);
    wsplit_k<<<(1*256*512 + 255)/256, 256>>>(e_W2, HID_, D_, 512, 256, 1, 0, weh2, wel2);
    wsplit_k<<<(NB_*256*256 + 255)/256, 256>>>(Wo, D_, D_,  256, 256, NB_, D_*D_,  woh, wol);
    wsplit_k<<<(NB_*512*256 + 255)/256, 256>>>(W1, D_, HID_, 256, 512, NB_, D_*HID_, w1h, w1l);
    wsplit_k<<<(NB_*256*512 + 255)/256, 256>>>(W2, HID_, D_, 512, 256, NB_, HID_*D_, w2h, w2l);
    qkvsplit_k<<<(NB_*768*256 + 255)/256, 256>>>(Wq, Wk, Wv, wqh, wql);
    bpackqkv_k<<<(NB_*768 + 255)/256, 256>>>(bq, bk, bv, bqkv);
    mask_k<<<(T_EMB + 7)/8, 256>>>(x, msk);

    // ---- XEmbed ----
    convx_k<<<(T_EMB*192 + 255)/256, 256>>>(x, ah, al);
    gemm_mma_k<0,0,0><<<dim3(4, 64), 256, SMEM_MMA_BYTES>>>(
        ah, al, weh1, wel1, 192, e_b1, nullptr, f, nullptr, nullptr, HID_, T_EMB, HID_);
    ln_split_k<1><<<(T_EMB + 7)/8, 256>>>(f, e_g1, e_bn1, ah, al, T_EMB, HID_, 512);
    gemm_mma_k<0,0,0><<<dim3(2, 64), 256, SMEM_MMA_BYTES>>>(
        ah, al, weh2, wel2, 512, e_b2, nullptr, y, nullptr, nullptr, D_, T_EMB, D_);
    ln_k<1><<<(T_EMB + 7)/8, 256>>>(y, e_g2, e_bn2, y, T_EMB, D_);
    assemble_k<<<(T_ALL*D_ + 255)/256, 256>>>(y, pos, cls, h);

    // ---- transformer blocks ----
    for (int i = 0; i < NB_; i++) {
        ln_split_k<0><<<(T_ALL + 7)/8, 256>>>(h, ln1_g + i*D_, ln1_b + i*D_, ah, al, T_ALL, D_, 256);
        gemm_mma_k<0,0,0><<<dim3(6, 65), 256, SMEM_MMA_BYTES>>>(
            ah, al, wqh + (size_t)i*768*256, wql + (size_t)i*768*256, 256,
            bqkv + i*768, nullptr, qkv, nullptr, nullptr, QKVN_, T_ALL, QKVN_);
        attn_k<<<dim3(H_, B_), 288>>>(qkv, msk, ah, al);
        gemm_mma_k<0,1,0><<<dim3(2, 65), 256, SMEM_MMA_BYTES>>>(
            ah, al, woh + (size_t)i*256*256, wol + (size_t)i*256*256, 256,
            bo + i*D_, h, h, nullptr, nullptr, D_, T_ALL, D_);
        ln_split_k<0><<<(T_ALL + 7)/8, 256>>>(h, ln2_g + i*D_, ln2_b + i*D_, ah, al, T_ALL, D_, 256);
        gemm_mma_k<1,0,1><<<dim3(4, 65), 256, SMEM_MMA_BYTES>>>(
            ah, al, w1h + (size_t)i*512*256, w1l + (size_t)i*512*256, 256,
            b1 + i*HID_, nullptr, nullptr, fh, fl, 512, T_ALL, HID_);
        gemm_mma_k<0,1,0><<<dim3(2, 65), 256, SMEM_MMA_BYTES>>>(
            fh, fl, w2h + (size_t)i*256*512, w2l + (size_t)i*256*512, 512,
            b2 + i*D_, h, h, nullptr, nullptr, D_, T_ALL, D_);
    }

    // ---- pool + logits ----
    pool_k<<<B_, 256>>>(h, msk, logit_W, logit_b, out);
}

// round 17
// speedup vs baseline: 2.3457x; 1.2429x over previous
#include <cuda_runtime.h>
#include <cuda_fp16.h>
#include <math.h>
#include <stdint.h>

// ---------------- problem constants ----------------
#define B_    32
#define L_    256
#define PD_   164
#define D_    240
#define H_    16
#define NB_   6
#define NC_   250
#define DK_   15
#define HID_  480
#define LP_   257
#define T_EMB (B_*L_)      // 8192
#define T_ALL (B_*LP_)     // 8224
#define MPAD_ 8320         // 65*128
#define SCALE_ 0.25819888974716115f
#define QKVN_ 720

// ---------------- scratch (device globals; zero-initialized at load) ----------------
__device__ float g_h   [T_ALL * D_];
__device__ float g_y   [T_EMB * D_];
__device__ float g_qkv [T_ALL * QKVN_];
__device__ float g_f   [T_EMB * HID_];
__device__ float g_mask[T_ALL];
__device__ float g_bqkv[NB_ * 768];

// fp16 activation buffers (padded rows)
__device__ __half g_a16[MPAD_ * 512];
__device__ __half g_f16[MPAD_ * 512];

// fp16 split transposed weights  Wt[l][Npad][Kpad]
__device__ __half g_weh1[512*192], g_wel1[512*192];
__device__ __half g_weh2[256*512], g_wel2[256*512];
__device__ __half g_wqh [NB_*768*256], g_wql [NB_*768*256];
__device__ __half g_woh [NB_*256*256], g_wol [NB_*256*256];
__device__ __half g_w1h [NB_*512*256], g_w1l [NB_*512*256];
__device__ __half g_w2h [NB_*256*512], g_w2l [NB_*256*512];

// ---------------- helpers ----------------
__device__ __forceinline__ uint32_t smem_u32(const void* p) {
    return (uint32_t)__cvta_generic_to_shared(p);
}
__device__ __forceinline__ void split_h16(float v, __half& hi, __half& lo) {
    hi = __float2half(v);
    lo = __float2half(v - __half2float(hi));
}
__device__ __forceinline__ void cp16(uint32_t dst, const void* src) {
    asm volatile("cp.async.cg.shared.global [%0], [%1], 16;"
                 :: "r"(dst), "l"(src) : "memory");
}
__device__ __forceinline__ void cp_commit() {
    asm volatile("cp.async.commit_group;" ::: "memory");
}
template<int N> __device__ __forceinline__ void cp_wait() {
    asm volatile("cp.async.wait_group %0;" :: "n"(N) : "memory");
}
__device__ __forceinline__ void ldm4(uint32_t* r, uint32_t addr) {
    asm volatile("ldmatrix.sync.aligned.m8n8.x4.shared.b16 {%0,%1,%2,%3}, [%4];"
                 : "=r"(r[0]), "=r"(r[1]), "=r"(r[2]), "=r"(r[3]) : "r"(addr));
}
__device__ __forceinline__ void mma_f16(float* c, const uint32_t* a,
                                        uint32_t b0, uint32_t b1) {
    asm volatile(
        "mma.sync.aligned.m16n8k16.row.col.f32.f16.f16.f32 "
        "{%0,%1,%2,%3}, {%4,%5,%6,%7}, {%8,%9}, {%0,%1,%2,%3};"
        : "+f"(c[0]), "+f"(c[1]), "+f"(c[2]), "+f"(c[3])
        : "r"(a[0]), "r"(a[1]), "r"(a[2]), "r"(a[3]), "r"(b0), "r"(b1));
}

// ---------------- mma.sync GEMM: 128x128 tile, 2-pass split-fp16 ----------------
// A: [rows][Kpad] fp16 (activations, rounded).  Bh/Bl: [Npad][Kpad] fp16 (weight split).
// D = A*Bh + A*Bl = A*B_exact-ish  (fp32 register accum).
// SPLIT=0: Cf[gm*ldc+gn] = acc + bias (+R) (relu), gm<M, gn<N.
// SPLIT=1: Ch fp16 at ld ldc; value 0 for gn in [N,ldc).
#define BUF_B  49152
#define SMEM_MMA_BYTES 98304

template<int SPLIT, int RES, int RELU>
__global__ __launch_bounds__(256, 2)
void gemm_mma_k(const __half* __restrict__ A,
                const __half* __restrict__ Bh, const __half* __restrict__ Bl,
                int Kpad,
                const float* __restrict__ bias, const float* __restrict__ R,
                float* __restrict__ Cf, __half* __restrict__ Ch,
                int ldc, int M, int N)
{
    extern __shared__ char sm[];
    const int tid  = threadIdx.x;
    const int lane = tid & 31;
    const int wid  = tid >> 5;
    const int wm   = wid >> 1;   // 0..3  -> m offset wm*32
    const int wn   = wid & 1;    // 0..1  -> n offset wn*64
    const int n0   = blockIdx.x * 128;
    const int m0   = blockIdx.y * 128;
    const uint32_t smb = smem_u32(sm);

    // ---- staging mapping: thread handles row r, half of its 128B chunk ----
    const int r    = tid >> 1;
    const int half = tid & 1;
    const uint32_t st_rb = (uint32_t)r * 128u;
    const uint32_t st_rx = (uint32_t)((r & 7) << 4);
    const uint32_t st_cx = (uint32_t)(half * 64);

    const __half* gsrc[3] = {
        A  + (size_t)m0 * Kpad,
        Bh + (size_t)n0 * Kpad,
        Bl + (size_t)n0 * Kpad };
    const uint32_t soff[3] = { 0u, 16384u, 32768u };

    const int KC = Kpad >> 6;

    // ---- fragment address precompute ----
    const uint32_t rxor = (uint32_t)((lane & 7) << 4);
    uint32_t aro[2], bro[4];
    #pragma unroll
    for (int mt = 0; mt < 2; mt++)
        aro[mt] = (uint32_t)(wm * 32 + mt * 16 + (lane & 15)) * 128u;
    #pragma unroll
    for (int nq = 0; nq < 4; nq++)
        bro[nq] = (uint32_t)(wn * 64 + nq * 16 + ((lane >> 4) << 3) + (lane & 7)) * 128u;
    const uint32_t kbA = (uint32_t)(((lane >> 4) & 1) * 16);
    const uint32_t kbB = (uint32_t)(((lane >> 3) & 1) * 16);

    float acc[2][8][4];
    #pragma unroll
    for (int mt = 0; mt < 2; mt++)
        #pragma unroll
        for (int nt = 0; nt < 8; nt++)
            #pragma unroll
            for (int e = 0; e < 4; e++) acc[mt][nt][e] = 0.f;

    // ---- prologue: stage chunk 0 ----
    {
        const size_t gofs = (size_t)r * Kpad + half * 32;
        #pragma unroll
        for (int t = 0; t < 3; t++) {
            const __half* s = gsrc[t] + gofs;
            uint32_t db = smb + soff[t] + st_rb;
            #pragma unroll
            for (int i = 0; i < 4; i++)
                cp16(db + ((st_cx + i * 16) ^ st_rx), s + i * 8);
        }
        cp_commit();
    }

    for (int c = 0; c < KC; c++) {
        if (c + 1 < KC) {
            const uint32_t bo = (uint32_t)((c + 1) & 1) * BUF_B;
            const size_t gofs = (size_t)r * Kpad + (size_t)(c + 1) * 64 + half * 32;
            #pragma unroll
            for (int t = 0; t < 3; t++) {
                const __half* s = gsrc[t] + gofs;
                uint32_t db = smb + bo + soff[t] + st_rb;
                #pragma unroll
                for (int i = 0; i < 4; i++)
                    cp16(db + ((st_cx + i * 16) ^ st_rx), s + i * 8);
            }
            cp_commit();
            cp_wait<1>();
        } else {
            cp_wait<0>();
        }
        __syncthreads();

        const uint32_t bo = (uint32_t)(c & 1) * BUF_B;
        const uint32_t sa  = smb + bo;
        const uint32_t sbh = smb + bo + 16384u;
        const uint32_t sbl = smb + bo + 32768u;

        #pragma unroll
        for (int ks = 0; ks < 4; ks++) {
            const uint32_t colA = ((uint32_t)(ks * 32) + kbA) ^ rxor;
            const uint32_t colB = ((uint32_t)(ks * 32) + kbB) ^ rxor;
            uint32_t ah[2][4];
            #pragma unroll
            for (int mt = 0; mt < 2; mt++)
                ldm4(ah[mt], sa + aro[mt] + colA);
            // hi pass
            {
                uint32_t bf[4][4];
                #pragma unroll
                for (int nq = 0; nq < 4; nq++)
                    ldm4(bf[nq], sbh + bro[nq] + colB);
                #pragma unroll
                for (int mt = 0; mt < 2; mt++)
                    #pragma unroll
                    for (int nt = 0; nt < 8; nt++) {
                        const int nq = nt >> 1;
                        const int p  = (nt & 1) * 2;
                        mma_f16(acc[mt][nt], ah[mt], bf[nq][p], bf[nq][p + 1]);
                    }
            }
            // lo pass
            {
                uint32_t bf[4][4];
                #pragma unroll
                for (int nq = 0; nq < 4; nq++)
                    ldm4(bf[nq], sbl + bro[nq] + colB);
                #pragma unroll
                for (int mt = 0; mt < 2; mt++)
                    #pragma unroll
                    for (int nt = 0; nt < 8; nt++) {
                        const int nq = nt >> 1;
                        const int p  = (nt & 1) * 2;
                        mma_f16(acc[mt][nt], ah[mt], bf[nq][p], bf[nq][p + 1]);
                    }
            }
        }
        __syncthreads();
    }

    // ---- epilogue: c0,c1 @ (row, col..col+1); c2,c3 @ (row+8, ..) ----
    const int qr = lane >> 2, qc = lane & 3;
    #pragma unroll
    for (int mt = 0; mt < 2; mt++) {
        const int rbase = m0 + wm * 32 + mt * 16 + qr;
        #pragma unroll
        for (int nt = 0; nt < 8; nt++) {
            const int col = n0 + wn * 64 + nt * 8 + qc * 2;
            const float* a4 = acc[mt][nt];
            if (!SPLIT) {
                if (col >= N) continue;
                const float2 bv = *(const float2*)(bias + col);
                #pragma unroll
                for (int hrow = 0; hrow < 2; hrow++) {
                    const int gm = rbase + hrow * 8;
                    if (gm >= M) continue;
                    float2 o;
                    o.x = a4[hrow * 2 + 0] + bv.x;
                    o.y = a4[hrow * 2 + 1] + bv.y;
                    if (RES) {
                        const float2 rr = *(const float2*)(R + (size_t)gm * ldc + col);
                        o.x += rr.x; o.y += rr.y;
                    }
                    if (RELU) { o.x = fmaxf(o.x, 0.f); o.y = fmaxf(o.y, 0.f); }
                    *(float2*)(Cf + (size_t)gm * ldc + col) = o;
                }
            } else {
                #pragma unroll
                for (int hrow = 0; hrow < 2; hrow++) {
                    const int gm = rbase + hrow * 8;
                    if (gm >= M) continue;
                    float v0 = 0.f, v1 = 0.f;
                    if (col < N)     v0 = a4[hrow * 2 + 0] + bias[col];
                    if (col + 1 < N) v1 = a4[hrow * 2 + 1] + bias[col + 1];
                    if (RELU) { v0 = fmaxf(v0, 0.f); v1 = fmaxf(v1, 0.f); }
                    __half2 h2;
                    h2.x = __float2half(v0);
                    h2.y = __float2half(v1);
                    *(__half2*)(Ch + (size_t)gm * ldc + col) = h2;
                }
            }
        }
    }
}

// ---------------- weight split/transpose: W[l][K][N] -> Wt[l][Npad][Kpad] hi/lo ----
__global__ void wsplit_k(const float* __restrict__ W, int K, int N, int Kpad, int Npad,
                         int nmat, int wstride,
                         __half* __restrict__ oh, __half* __restrict__ ol)
{
    int idx = blockIdx.x * blockDim.x + threadIdx.x;
    int total = nmat * Npad * Kpad;
    if (idx >= total) return;
    int k = idx % Kpad;
    int n = (idx / Kpad) % Npad;
    int l = idx / (Kpad * Npad);
    float v = (k < K && n < N) ? W[(size_t)l * wstride + (size_t)k * N + n] : 0.f;
    __half hi, lo; split_h16(v, hi, lo);
    oh[idx] = hi; ol[idx] = lo;
}

__global__ void qkvsplit_k(const float* __restrict__ Wq, const float* __restrict__ Wk,
                           const float* __restrict__ Wv,
                           __half* __restrict__ oh, __half* __restrict__ ol)
{
    int idx = blockIdx.x * blockDim.x + threadIdx.x;
    const int total = NB_ * 768 * 256;
    if (idx >= total) return;
    int k = idx & 255;
    int n = (idx >> 8) % 768;
    int l = idx / (256 * 768);
    float v = 0.f;
    if (k < D_ && n < 720) {
        const float* src = (n < 240) ? Wq : ((n < 480) ? Wk : Wv);
        v = src[(size_t)l * D_ * D_ + (size_t)k * D_ + (n % 240)];
    }
    __half hi, lo; split_h16(v, hi, lo);
    oh[idx] = hi; ol[idx] = lo;
}

__global__ void bpackqkv_k(const float* __restrict__ bq, const float* __restrict__ bk,
                           const float* __restrict__ bv, float* __restrict__ o)
{
    int idx = blockIdx.x * blockDim.x + threadIdx.x;
    if (idx >= NB_ * 768) return;
    int c = idx % 768, l = idx / 768;
    float v = 0.f;
    if (c < 720) {
        const float* src = (c < 240) ? bq : ((c < 480) ? bk : bv);
        v = src[l * D_ + (c % 240)];
    }
    o[idx] = v;
}

// ---------------- x -> fp16 (ld 192, zero pad) ----------------
__global__ void convx_k(const float* __restrict__ x, __half* __restrict__ o)
{
    int idx = blockIdx.x * blockDim.x + threadIdx.x;
    const int total = T_EMB * 192;
    if (idx >= total) return;
    int k = idx % 192, t = idx / 192;
    float v = (k < PD_) ? x[(size_t)t * PD_ + k] : 0.f;
    o[idx] = __float2half(v);
}

// ---------------- LayerNorm fp32 -> fp16 (warp per token) ----------------
template<int RELU>
__global__ void ln_half_k(const float* __restrict__ X, const float* __restrict__ g,
                          const float* __restrict__ b, __half* __restrict__ Y,
                          int T, int N, int LDO)
{
    int wid = threadIdx.x >> 5, lane = threadIdx.x & 31;
    int t = blockIdx.x * (blockDim.x >> 5) + wid;
    if (t >= T) return;
    const float* x = X + (size_t)t * N;
    float s = 0.f;
    for (int i = lane; i < N; i += 32) s += x[i];
    #pragma unroll
    for (int o = 16; o; o >>= 1) s += __shfl_xor_sync(~0u, s, o);
    float mean = s / (float)N;
    float v = 0.f;
    for (int i = lane; i < N; i += 32) { float d = x[i] - mean; v = fmaf(d, d, v); }
    #pragma unroll
    for (int o = 16; o; o >>= 1) v += __shfl_xor_sync(~0u, v, o);
    float inv = rsqrtf(v / (float)N + 1e-5f);
    __half* y = Y + (size_t)t * LDO;
    for (int i = lane; i < LDO; i += 32) {
        float r = 0.f;
        if (i < N) {
            r = (x[i] - mean) * inv * g[i] + b[i];
            if (RELU) r = fmaxf(r, 0.f);
        }
        y[i] = __float2half(r);
    }
}

// ---------------- LayerNorm fp32 -> fp32 (+relu) ----------------
template<int RELU>
__global__ void ln_k(const float* __restrict__ X, const float* __restrict__ g,
                     const float* __restrict__ b, float* __restrict__ Y, int T, int N)
{
    int wid = threadIdx.x >> 5, lane = threadIdx.x & 31;
    int t = blockIdx.x * (blockDim.x >> 5) + wid;
    if (t >= T) return;
    const float* x = X + (size_t)t * N;
    float s = 0.f;
    for (int i = lane; i < N; i += 32) s += x[i];
    #pragma unroll
    for (int o = 16; o; o >>= 1) s += __shfl_xor_sync(~0u, s, o);
    float mean = s / (float)N;
    float v = 0.f;
    for (int i = lane; i < N; i += 32) { float d = x[i] - mean; v = fmaf(d, d, v); }
    #pragma unroll
    for (int o = 16; o; o >>= 1) v += __shfl_xor_sync(~0u, v, o);
    float inv = rsqrtf(v / (float)N + 1e-5f);
    float* y = Y + (size_t)t * N;
    for (int i = lane; i < N; i += 32) {
        float r = (x[i] - mean) * inv * g[i] + b[i];
        if (RELU) r = fmaxf(r, 0.f);
        y[i] = r;
    }
}

// ---------------- padding mask ----------------
__global__ void mask_k(const float* __restrict__ x, float* __restrict__ mask)
{
    int wid = threadIdx.x >> 5, lane = threadIdx.x & 31;
    int token = blockIdx.x * (blockDim.x >> 5) + wid;
    if (token >= T_EMB) return;
    int b = token / L_, l = token % L_;
    const float* row = x + (size_t)token * PD_;
    float m = -3.4e38f;
    for (int i = lane; i < PD_; i += 32) m = fmaxf(m, row[i]);
    #pragma unroll
    for (int o = 16; o; o >>= 1) m = fmaxf(m, __shfl_xor_sync(~0u, m, o));
    if (lane == 0) {
        mask[b * LP_ + 1 + l] = (m == 0.f) ? 1.f : 0.f;
        if (l == 0) mask[b * LP_] = 0.f;
    }
}

// ---------------- assemble ----------------
__global__ void assemble_k(const float* __restrict__ t2, const float* __restrict__ pos,
                           const float* __restrict__ cls, float* __restrict__ h)
{
    int idx = blockIdx.x * blockDim.x + threadIdx.x;
    if (idx >= T_ALL * D_) return;
    int d = idx % D_;
    int bt = idx / D_;
    int t = bt % LP_;
    int b = bt / LP_;
    float v;
    if (t == 0) v = cls[d];
    else        v = t2[((size_t)b * L_ + (t - 1)) * D_ + d] + pos[(size_t)(t - 1) * D_ + d];
    h[idx] = v;
}

// ---------------- attention: thread-per-query online softmax, fp16 output ----------
__global__ __launch_bounds__(288)
void attn_k(const float* __restrict__ qkv, const float* __restrict__ mask,
            __half* __restrict__ O)
{
    const int hh = blockIdx.x;
    const int b  = blockIdx.y;
    __shared__ __align__(16) float sQ[LP_][16];
    __shared__ __align__(16) float sK[LP_][16];
    __shared__ __align__(16) float sV[LP_][16];
    __shared__ float sM[LP_];

    const int tid = threadIdx.x;
    for (int idx = tid; idx < LP_ * DK_; idx += 288) {
        int t = idx / DK_, d = idx % DK_;
        size_t g = (size_t)(b * LP_ + t) * QKVN_ + hh * DK_ + d;
        sQ[t][d] = qkv[g] * SCALE_;        // fold scale into Q
        sK[t][d] = qkv[g + D_];
        sV[t][d] = qkv[g + 2 * D_];
    }
    for (int t = tid; t < LP_; t += 288) {
        sQ[t][15] = 0.f; sK[t][15] = 0.f; sV[t][15] = 0.f;
        sM[t] = mask[b * LP_ + t];
    }
    __syncthreads();

    if (tid >= LP_) return;

    float4 q0 = *(const float4*)&sQ[tid][0];
    float4 q1 = *(const float4*)&sQ[tid][4];
    float4 q2 = *(const float4*)&sQ[tid][8];
    float4 q3 = *(const float4*)&sQ[tid][12];

    float m = -3.4e38f, l = 0.f;
    float4 o0 = {0,0,0,0}, o1 = {0,0,0,0}, o2 = {0,0,0,0}, o3 = {0,0,0,0};

    for (int j = 0; j < LP_; j++) {
        float4 k0 = *(const float4*)&sK[j][0];
        float4 k1 = *(const float4*)&sK[j][4];
        float4 k2 = *(const float4*)&sK[j][8];
        float4 k3 = *(const float4*)&sK[j][12];
        float s = q0.x*k0.x + q0.y*k0.y + q0.z*k0.z + q0.w*k0.w
                + q1.x*k1.x + q1.y*k1.y + q1.z*k1.z + q1.w*k1.w
                + q2.x*k2.x + q2.y*k2.y + q2.z*k2.z + q2.w*k2.w
                + q3.x*k3.x + q3.y*k3.y + q3.z*k3.z;
        s = (sM[j] != 0.f) ? -10000.f : s;
        if (s > m) {
            float f = __expf(m - s);
            m = s; l *= f;
            o0.x *= f; o0.y *= f; o0.z *= f; o0.w *= f;
            o1.x *= f; o1.y *= f; o1.z *= f; o1.w *= f;
            o2.x *= f; o2.y *= f; o2.z *= f; o2.w *= f;
            o3.x *= f; o3.y *= f; o3.z *= f; o3.w *= f;
        }
        float p = __expf(s - m);
        l += p;
        float4 v0 = *(const float4*)&sV[j][0];
        float4 v1 = *(const float4*)&sV[j][4];
        float4 v2 = *(const float4*)&sV[j][8];
        float4 v3 = *(const float4*)&sV[j][12];
        o0.x = fmaf(p, v0.x, o0.x); o0.y = fmaf(p, v0.y, o0.y);
        o0.z = fmaf(p, v0.z, o0.z); o0.w = fmaf(p, v0.w, o0.w);
        o1.x = fmaf(p, v1.x, o1.x); o1.y = fmaf(p, v1.y, o1.y);
        o1.z = fmaf(p, v1.z, o1.z); o1.w = fmaf(p, v1.w, o1.w);
        o2.x = fmaf(p, v2.x, o2.x); o2.y = fmaf(p, v2.y, o2.y);
        o2.z = fmaf(p, v2.z, o2.z); o2.w = fmaf(p, v2.w, o2.w);
        o3.x = fmaf(p, v3.x, o3.x); o3.y = fmaf(p, v3.y, o3.y);
        o3.z = fmaf(p, v3.z, o3.z);
    }
    float inv = 1.f / l;
    float vals[15] = { o0.x, o0.y, o0.z, o0.w, o1.x, o1.y, o1.z, o1.w,
                       o2.x, o2.y, o2.z, o2.w, o3.x, o3.y, o3.z };
    size_t base = (size_t)(b * LP_ + tid) * 256 + hh * DK_;
    #pragma unroll
    for (int d = 0; d < 15; d++)
        O[base + d] = __float2half(vals[d] * inv);
}

// ---------------- masked mean pool + logits ----------------
__global__ __launch_bounds__(256)
void pool_k(const float* __restrict__ h, const float* __restrict__ mask,
            const float* __restrict__ lw, const float* __restrict__ lb,
            float* __restrict__ out)
{
    int b = blockIdx.x;
    __shared__ float sp[D_];
    __shared__ float smm[LP_];
    int tid = threadIdx.x;
    for (int t = tid; t < LP_; t += blockDim.x) smm[t] = mask[b * LP_ + t];
    __syncthreads();
    float cnt = 0.f;
    for (int t = 0; t < LP_; t++) cnt += 1.f - smm[t];
    if (tid < D_) {
        float acc = 0.f;
        for (int t = 0; t < LP_; t++) {
            float w = 1.f - smm[t];
            acc = fmaf(h[((size_t)b * LP_ + t) * D_ + tid], w, acc);
        }
        sp[tid] = acc / cnt;
    }
    __syncthreads();
    if (tid < NC_) {
        float acc = lb[tid];
        for (int d = 0; d < D_; d++) acc = fmaf(sp[d], lw[(size_t)d * NC_ + tid], acc);
        out[b * NC_ + tid] = acc;
    }
}

// ---------------- host ----------------
extern "C" void kernel_launch(void* const* d_in, const int* in_sizes, int n_in,
                              void* d_out, int out_size)
{
    const float* x       = (const float*)d_in[0];
    const float* pos     = (const float*)d_in[1];
    const float* cls     = (const float*)d_in[2];
    const float* e_W1    = (const float*)d_in[3];
    const float* e_b1    = (const float*)d_in[4];
    const float* e_g1    = (const float*)d_in[5];
    const float* e_bn1   = (const float*)d_in[6];
    const float* e_W2    = (const float*)d_in[7];
    const float* e_b2    = (const float*)d_in[8];
    const float* e_g2    = (const float*)d_in[9];
    const float* e_bn2   = (const float*)d_in[10];
    const float* ln1_g   = (const float*)d_in[11];
    const float* ln1_b   = (const float*)d_in[12];
    const float* Wq      = (const float*)d_in[13];
    const float* bq      = (const float*)d_in[14];
    const float* Wk      = (const float*)d_in[15];
    const float* bk      = (const float*)d_in[16];
    const float* Wv      = (const float*)d_in[17];
    const float* bv      = (const float*)d_in[18];
    const float* Wo      = (const float*)d_in[19];
    const float* bo      = (const float*)d_in[20];
    const float* ln2_g   = (const float*)d_in[21];
    const float* ln2_b   = (const float*)d_in[22];
    const float* W1      = (const float*)d_in[23];
    const float* b1      = (const float*)d_in[24];
    const float* W2      = (const float*)d_in[25];
    const float* b2      = (const float*)d_in[26];
    const float* logit_W = (const float*)d_in[27];
    const float* logit_b = (const float*)d_in[28];
    float* out = (float*)d_out;

    float *h, *y, *qkv, *f, *msk, *bqkv;
    __half *a16, *f16;
    __half *weh1, *wel1, *weh2, *wel2, *wqh, *wql, *woh, *wol, *w1h, *w1l, *w2h, *w2l;
    cudaGetSymbolAddress((void**)&h,    g_h);
    cudaGetSymbolAddress((void**)&y,    g_y);
    cudaGetSymbolAddress((void**)&qkv,  g_qkv);
    cudaGetSymbolAddress((void**)&f,    g_f);
    cudaGetSymbolAddress((void**)&msk,  g_mask);
    cudaGetSymbolAddress((void**)&bqkv, g_bqkv);
    cudaGetSymbolAddress((void**)&a16,  g_a16);
    cudaGetSymbolAddress((void**)&f16,  g_f16);
    cudaGetSymbolAddress((void**)&weh1, g_weh1);
    cudaGetSymbolAddress((void**)&wel1, g_wel1);
    cudaGetSymbolAddress((void**)&weh2, g_weh2);
    cudaGetSymbolAddress((void**)&wel2, g_wel2);
    cudaGetSymbolAddress((void**)&wqh,  g_wqh);
    cudaGetSymbolAddress((void**)&wql,  g_wql);
    cudaGetSymbolAddress((void**)&woh,  g_woh);
    cudaGetSymbolAddress((void**)&wol,  g_wol);
    cudaGetSymbolAddress((void**)&w1h,  g_w1h);
    cudaGetSymbolAddress((void**)&w1l,  g_w1l);
    cudaGetSymbolAddress((void**)&w2h,  g_w2h);
    cudaGetSymbolAddress((void**)&w2l,  g_w2l);

    cudaFuncSetAttribute(gemm_mma_k<0,0,0>, cudaFuncAttributeMaxDynamicSharedMemorySize, SMEM_MMA_BYTES);
    cudaFuncSetAttribute(gemm_mma_k<0,1,0>, cudaFuncAttributeMaxDynamicSharedMemorySize, SMEM_MMA_BYTES);
    cudaFuncSetAttribute(gemm_mma_k<1,0,1>, cudaFuncAttributeMaxDynamicSharedMemorySize, SMEM_MMA_BYTES);

    // ---- weight conversion (per call; weights are inputs) ----
    wsplit_k<<<(1*512*192 + 255)/256, 256>>>(e_W1, PD_, HID_, 192, 512, 1, 0, weh1, wel1);
    wsplit_k<<<(1*256*512 + 255)/256, 256>>>(e_W2, HID_, D_, 512, 256, 1, 0, weh2, wel2);
    wsplit_k<<<(NB_*256*256 + 255)/256, 256>>>(Wo, D_, D_,  256, 256, NB_, D_*D_,  woh, wol);
    wsplit_k<<<(NB_*512*256 + 255)/256, 256>>>(W1, D_, HID_, 256, 512, NB_, D_*HID_, w1h, w1l);
    wsplit_k<<<(NB_*256*512 + 255)/256, 256>>>(W2, HID_, D_, 512, 256, NB_, HID_*D_, w2h, w2l);
    qkvsplit_k<<<(NB_*768*256 + 255)/256, 256>>>(Wq, Wk, Wv, wqh, wql);
    bpackqkv_k<<<(NB_*768 + 255)/256, 256>>>(bq, bk, bv, bqkv);
    mask_k<<<(T_EMB + 7)/8, 256>>>(x, msk);

    // ---- XEmbed ----
    convx_k<<<(T_EMB*192 + 255)/256, 256>>>(x, a16);
    gemm_mma_k<0,0,0><<<dim3(4, 64), 256, SMEM_MMA_BYTES>>>(
        a16, weh1, wel1, 192, e_b1, nullptr, f, nullptr, HID_, T_EMB, HID_);
    ln_half_k<1><<<(T_EMB + 7)/8, 256>>>(f, e_g1, e_bn1, a16, T_EMB, HID_, 512);
    gemm_mma_k<0,0,0><<<dim3(2, 64), 256, SMEM_MMA_BYTES>>>(
        a16, weh2, wel2, 512, e_b2, nullptr, y, nullptr, D_, T_EMB, D_);
    ln_k<1><<<(T_EMB + 7)/8, 256>>>(y, e_g2, e_bn2, y, T_EMB, D_);
    assemble_k<<<(T_ALL*D_ + 255)/256, 256>>>(y, pos, cls, h);

    // ---- transformer blocks ----
    for (int i = 0; i < NB_; i++) {
        ln_half_k<0><<<(T_ALL + 7)/8, 256>>>(h, ln1_g + i*D_, ln1_b + i*D_, a16, T_ALL, D_, 256);
        gemm_mma_k<0,0,0><<<dim3(6, 65), 256, SMEM_MMA_BYTES>>>(
            a16, wqh + (size_t)i*768*256, wql + (size_t)i*768*256, 256,
            bqkv + i*768, nullptr, qkv, nullptr, QKVN_, T_ALL, QKVN_);
        attn_k<<<dim3(H_, B_), 288>>>(qkv, msk, a16);
        gemm_mma_k<0,1,0><<<dim3(2, 65), 256, SMEM_MMA_BYTES>>>(
            a16, woh + (size_t)i*256*256, wol + (size_t)i*256*256, 256,
            bo + i*D_, h, h, nullptr, D_, T_ALL, D_);
        ln_half_k<0><<<(T_ALL + 7)/8, 256>>>(h, ln2_g + i*D_, ln2_b + i*D_, a16, T_ALL, D_, 256);
        gemm_mma_k<1,0,1><<<dim3(4, 65), 256, SMEM_MMA_BYTES>>>(
            a16, w1h + (size_t)i*512*256, w1l + (size_t)i*512*256, 256,
            b1 + i*HID_, nullptr, nullptr, f16, 512, T_ALL, HID_);
        gemm_mma_k<0,1,0><<<dim3(2, 65), 256, SMEM_MMA_BYTES>>>(
            f16, w2h + (size_t)i*256*512, w2l + (size_t)i*256*512, 512,
            b2 + i*D_, h, h, nullptr, D_, T_ALL, D_);
    }

    // ---- pool + logits ----
    pool_k<<<B_, 256>>>(h, msk, logit_W, logit_b, out);
}